// round 1
// baseline (speedup 1.0000x reference)
#include <cuda_runtime.h>

#define BLK     256
#define M_TILE  64
#define N_TILE  128
#define K_DIM   256
#define K_CHUNK 64
#define KPC     (K_CHUNK/2)     // 32 k-pairs per chunk
#define VOCAB   1024
#define N_Q     32768           // 64*32*16 queries
#define AV      4096            // embed_dim * tokens_per_layer
#define PITCH_B 129             // padded float2 pitch for B tile

__device__ float g_sz[N_Q];
__device__ float g_se[VOCAB];

// ---------------- prep: ||z||^2 per query, ||e||^2 per vocab row ----------------
__global__ void prep_kernel(const float* __restrict__ x, const float* __restrict__ emb) {
    int idx = blockIdx.x * blockDim.x + threadIdx.x;
    if (idx < N_Q) {
        int bl = idx >> 4, v = idx & 15;
        const float* p = x + (size_t)bl * AV + v;
        double s = 0.0;
        #pragma unroll 8
        for (int k = 0; k < K_DIM; ++k) { float z = p[k * 16]; s += (double)z * (double)z; }
        g_sz[idx] = (float)s;
    } else if (idx < N_Q + VOCAB) {
        int n = idx - N_Q;
        const float4* p = (const float4*)(emb + (size_t)n * K_DIM);
        double s = 0.0;
        #pragma unroll 8
        for (int q = 0; q < K_DIM / 4; ++q) {
            float4 e = p[q];
            s += (double)e.x * e.x + (double)e.y * e.y + (double)e.z * e.z + (double)e.w * e.w;
        }
        g_se[n] = (float)s;
    }
}

// packed fp32x2 FMA (Blackwell FFMA2)
__device__ __forceinline__ void fma2(unsigned long long& d, unsigned long long a, unsigned long long b) {
    asm("fma.rn.f32x2 %0, %1, %2, %0;" : "+l"(d) : "l"(a), "l"(b));
}

extern __shared__ unsigned char smem_raw[];

// ---------------- main: fused dist-GEMM + argmin + gather/writeback ----------------
__global__ void __launch_bounds__(BLK, 1)
vq_kernel(const float* __restrict__ x, const float* __restrict__ emb,
          float* __restrict__ out, int out_size) {
    // smem layout (bytes):
    //   [0,65536)          A tile: [128 kp][64 m] float2 (full K resident)
    //   [65536,131584)     B tiles: 2 x [32 kp][129 pitch] float2 (double buffer)
    //   [131584,135680)    se[1024]
    //   [135680,135936)    tokens[64]
    float*               As  = (float*)smem_raw;
    unsigned long long*  AsU = (unsigned long long*)smem_raw;
    float2*              Bs  = (float2*)(smem_raw + 65536);
    unsigned long long*  BsU = (unsigned long long*)(smem_raw + 65536);
    float*               se_s = (float*)(smem_raw + 131584);
    int*                 tok_s = (int*)(smem_raw + 135680);

    const int tid = threadIdx.x;
    const int tx = tid & 15, ty = tid >> 4;
    const int m0 = blockIdx.x * M_TILE;

    // ---- load A tile (64 queries x 256 dims) into [kp][m] packed layout
    {
        int ml = tid & 63, g = tid >> 6;
        int mg = m0 + ml;
        int bl = mg >> 4, v = mg & 15;
        const float* p = x + (size_t)bl * AV + v;
        #pragma unroll 8
        for (int kk = 0; kk < 64; ++kk) {
            int k = g * 64 + kk;
            As[(k >> 1) * (M_TILE * 2) + ml * 2 + (k & 1)] = p[k * 16];
        }
    }
    // ---- stage se
    for (int i = tid; i < VOCAB; i += BLK) se_s[i] = g_se[i];

    // ---- load first B chunk (tile 0, chunk 0)
    const int kq = tid & 15, nr = tid >> 4;
    float4 ebuf[8];
    {
        const float* src = emb + (size_t)nr * K_DIM + kq * 4;
        #pragma unroll
        for (int r = 0; r < 8; ++r) ebuf[r] = *(const float4*)(src + (size_t)r * 16 * K_DIM);
        #pragma unroll
        for (int r = 0; r < 8; ++r) {
            int nl = nr + r * 16;
            Bs[(2 * kq)     * PITCH_B + nl] = make_float2(ebuf[r].x, ebuf[r].y);
            Bs[(2 * kq + 1) * PITCH_B + nl] = make_float2(ebuf[r].z, ebuf[r].w);
        }
    }
    __syncthreads();

    float szr[4];
    #pragma unroll
    for (int i = 0; i < 4; ++i) szr[i] = g_sz[m0 + ty + 16 * i];

    unsigned long long acc[4][8];
    #pragma unroll
    for (int i = 0; i < 4; ++i)
        #pragma unroll
        for (int j = 0; j < 8; ++j) acc[i][j] = 0ull;

    float bestD[4]; int bestN[4];
    #pragma unroll
    for (int i = 0; i < 4; ++i) { bestD[i] = __int_as_float(0x7f800000); bestN[i] = 0; }

    int buf = 0;
    const int NSTAGE = (VOCAB / N_TILE) * (K_DIM / K_CHUNK);  // 32
    for (int s = 0; s < NSTAGE; ++s) {
        // prefetch next chunk (gmem -> regs)
        if (s + 1 < NSTAGE) {
            int t = (s + 1) >> 2, c = (s + 1) & 3;
            const float* src = emb + (size_t)(t * N_TILE + nr) * K_DIM + c * K_CHUNK + kq * 4;
            #pragma unroll
            for (int r = 0; r < 8; ++r)
                ebuf[r] = *(const float4*)(src + (size_t)r * 16 * K_DIM);
        }
        // compute current chunk
        {
            int c = s & 3;
            const unsigned long long* Ab = AsU + (c * KPC) * M_TILE;
            const unsigned long long* Bb = BsU + buf * (KPC * PITCH_B);
            #pragma unroll 4
            for (int kp = 0; kp < KPC; ++kp) {
                unsigned long long a2[4], b2[8];
                #pragma unroll
                for (int i = 0; i < 4; ++i) a2[i] = Ab[kp * M_TILE + ty + 16 * i];
                #pragma unroll
                for (int j = 0; j < 8; ++j) b2[j] = Bb[kp * PITCH_B + tx + 16 * j];
                #pragma unroll
                for (int i = 0; i < 4; ++i)
                    #pragma unroll
                    for (int j = 0; j < 8; ++j)
                        fma2(acc[i][j], a2[i], b2[j]);
            }
        }
        // store prefetched chunk into the other buffer
        if (s + 1 < NSTAGE) {
            float2* Bd = Bs + (buf ^ 1) * (KPC * PITCH_B);
            #pragma unroll
            for (int r = 0; r < 8; ++r) {
                int nl = nr + r * 16;
                Bd[(2 * kq)     * PITCH_B + nl] = make_float2(ebuf[r].x, ebuf[r].y);
                Bd[(2 * kq + 1) * PITCH_B + nl] = make_float2(ebuf[r].z, ebuf[r].w);
            }
        }
        // end of vocab tile: fold into running argmin (n ascending -> strict '<' keeps first index)
        if ((s & 3) == 3) {
            int n0t = (s >> 2) * N_TILE;
            #pragma unroll
            for (int i = 0; i < 4; ++i) {
                float szv = szr[i];
                #pragma unroll
                for (int j = 0; j < 8; ++j) {
                    unsigned long long a = acc[i][j];
                    float dot = __uint_as_float((unsigned)a) + __uint_as_float((unsigned)(a >> 32));
                    int n = n0t + tx + 16 * j;
                    float t = szv + se_s[n];              // fl(sz + se): matches ref rounding
                    float dist = fmaf(-2.0f, dot, t);     // == fl(t - fl(2*dot)) since *2 exact
                    if (dist < bestD[i]) { bestD[i] = dist; bestN[i] = n; }
                    acc[i][j] = 0ull;
                }
            }
        }
        __syncthreads();
        buf ^= 1;
    }

    // cross-lane argmin within each 16-lane group (same m row), tie -> lower index
    #pragma unroll
    for (int i = 0; i < 4; ++i) {
        float d = bestD[i]; int n = bestN[i];
        #pragma unroll
        for (int off = 8; off; off >>= 1) {
            float d2 = __shfl_xor_sync(0xffffffffu, d, off, 16);
            int   n2 = __shfl_xor_sync(0xffffffffu, n, off, 16);
            if (d2 < d || (d2 == d && n2 < n)) { d = d2; n = n2; }
        }
        if (tx == 0) tok_s[ty + 16 * i] = n;
    }
    __syncthreads();

    // ---- outputs: z_q | decoder_input | tokens (as float), guarded by out_size
    float* out_zq  = out;
    float* out_dec = out + (size_t)N_Q * K_DIM;
    float* out_tok = out + (size_t)2 * N_Q * K_DIM;
    const long long need_dec = 2LL * N_Q * K_DIM;
    const bool wd = (long long)out_size >= need_dec;
    const bool wt = (long long)out_size >= need_dec + N_Q;

    if (wt && tid < M_TILE) out_tok[m0 + tid] = (float)tok_s[tid];

    int bl0 = m0 >> 4;
    #pragma unroll
    for (int g = 0; g < 4; ++g) {
        const float* xr = x + (size_t)(bl0 + g) * AV;
        float* zr = out_zq  + (size_t)(bl0 + g) * AV;
        float* dr = out_dec + (size_t)(bl0 + g) * AV;
        for (int idx = tid * 4; idx < AV; idx += BLK * 4) {
            int a = idx >> 4, v0 = idx & 15;
            float4 xv = *(const float4*)(xr + idx);
            float4 q;
            q.x = emb[(size_t)tok_s[g * 16 + v0 + 0] * K_DIM + a];
            q.y = emb[(size_t)tok_s[g * 16 + v0 + 1] * K_DIM + a];
            q.z = emb[(size_t)tok_s[g * 16 + v0 + 2] * K_DIM + a];
            q.w = emb[(size_t)tok_s[g * 16 + v0 + 3] * K_DIM + a];
            *(float4*)(zr + idx) = q;
            if (wd) {
                float4 dv;
                dv.x = xv.x + (q.x - xv.x);
                dv.y = xv.y + (q.y - xv.y);
                dv.z = xv.z + (q.z - xv.z);
                dv.w = xv.w + (q.w - xv.w);
                *(float4*)(dr + idx) = dv;
            }
        }
    }
}

extern "C" void kernel_launch(void* const* d_in, const int* in_sizes, int n_in,
                              void* d_out, int out_size) {
    const float* x   = (const float*)d_in[0];
    const float* emb = (const float*)d_in[1];
    float* out = (float*)d_out;
    (void)in_sizes; (void)n_in;

    const int smem_bytes = 135936;
    cudaFuncSetAttribute(vq_kernel, cudaFuncAttributeMaxDynamicSharedMemorySize, smem_bytes);

    prep_kernel<<<(N_Q + VOCAB + 255) / 256, 256>>>(x, emb);
    vq_kernel<<<N_Q / M_TILE, BLK, smem_bytes>>>(x, emb, out, out_size);
}

// round 2
// speedup vs baseline: 1.0545x; 1.0545x over previous
#include <cuda_runtime.h>
#include <cstdint>

#define BLK     256
#define M_TILE  64
#define N_TILE  128
#define K_DIM   256
#define VOCAB   1024
#define N_Q     32768
#define AV      4096
#define PA4     65          // A pitch in float4 units (64 + 1 pad)
#define PB4     9           // B pitch in float4 units (8 + 1 pad)

#define A_OFF        0
#define A_BYTES      (M_TILE * PA4 * 16)      // 66560
#define B_OFF        A_BYTES
#define B_TILE_BYTES (N_TILE * PB4 * 16)      // 18432
#define SE_OFF       (B_OFF + 2 * B_TILE_BYTES)   // 103424
#define SCR_OFF      (SE_OFF + VOCAB * 4)         // 107520
#define SZF_OFF      (SCR_OFF + 2048)             // 109568
#define TOK_OFF      (SZF_OFF + 256)              // 109824
#define SMEM_BYTES   (TOK_OFF + 256)              // 110080

typedef unsigned long long ull;

__device__ float g_se[VOCAB];

// ---------------- prep: ||e||^2 per vocab row (tiny, fp64) ----------------
__global__ void prep_se(const float* __restrict__ emb) {
    int n = blockIdx.x * blockDim.x + threadIdx.x;
    if (n < VOCAB) {
        const float4* p = (const float4*)(emb + (size_t)n * K_DIM);
        double s = 0.0;
        #pragma unroll 8
        for (int q = 0; q < K_DIM / 4; ++q) {
            float4 e = p[q];
            s += (double)e.x * e.x + (double)e.y * e.y + (double)e.z * e.z + (double)e.w * e.w;
        }
        g_se[n] = (float)s;
    }
}

// packed fp32x2 FMA (Blackwell FFMA2)
__device__ __forceinline__ void fma2(ull& d, ull a, ull b) {
    asm("fma.rn.f32x2 %0, %1, %2, %0;" : "+l"(d) : "l"(a), "l"(b));
}
// cp.async 16B gmem->smem
__device__ __forceinline__ void cpa16(uint32_t dst, const void* src) {
    asm volatile("cp.async.cg.shared.global [%0], [%1], 16;" :: "r"(dst), "l"(src));
}
__device__ __forceinline__ void cp_commit() { asm volatile("cp.async.commit_group;"); }
__device__ __forceinline__ void cp_wait0()  { asm volatile("cp.async.wait_group 0;" ::: "memory"); }

__device__ __forceinline__ uint32_t smem_u32(const void* p) {
    uint32_t a;
    asm("{ .reg .u64 t; cvta.to.shared.u64 t, %1; cvt.u32.u64 %0, t; }" : "=r"(a) : "l"(p));
    return a;
}

// exact-product compensated accumulate: (s,c) += z*z
__device__ __forceinline__ void sq_acc(float z, float& s, float& c) {
    float p = __fmul_rn(z, z);
    float e = fmaf(z, z, -p);          // exact product error
    float t = __fadd_rn(s, p);         // TwoSum
    float bb = __fsub_rn(t, s);
    float err = __fadd_rn(__fsub_rn(s, __fsub_rn(t, bb)), __fsub_rn(p, bb));
    s = t;
    c = __fadd_rn(c, __fadd_rn(err, e));
}

extern __shared__ unsigned char smem_raw[];

__global__ void __launch_bounds__(BLK, 2)
vq_kernel(const float* __restrict__ x, const float* __restrict__ emb,
          float* __restrict__ out, int out_size) {
    float*  As_f  = (float*)(smem_raw + A_OFF);
    float*  se_s  = (float*)(smem_raw + SE_OFF);
    float*  scr   = (float*)(smem_raw + SCR_OFF);
    float*  szf   = (float*)(smem_raw + SZF_OFF);
    int*    tok_s = (int*)(smem_raw + TOK_OFF);
    const uint32_t sb = smem_u32(smem_raw);

    const int tid = threadIdx.x;
    const int tx = tid & 31;           // n-lane
    const int mb = (tid >> 5) * 8;     // this warp's 8 m rows
    const int m0 = blockIdx.x * M_TILE;

    // B prefetch thread mapping: kq = float4 column within 32-float chunk, rows nl = nr + 32r
    const int kq = tid & 7, nr = tid >> 3;

    // ---- issue cp.async for tile0/chunk0 into buffer 0
    {
        const float* src = emb + (size_t)nr * K_DIM + kq * 4;
        #pragma unroll
        for (int r = 0; r < 4; ++r) {
            uint32_t dst = sb + B_OFF + ((nr + 32 * r) * PB4 + kq) * 16;
            cpa16(dst, src + (size_t)r * 32 * K_DIM);
        }
        cp_commit();
    }

    // ---- load A tile: 4 bl-rows of x, scatter into [m][k] layout (pitch 260 floats)
    {
        const float* xb = x + (size_t)(blockIdx.x * 4) * AV;
        #pragma unroll
        for (int it = 0; it < 16; ++it) {
            int idx = tid * 4 + it * (BLK * 4);      // 0..16383
            int g = idx >> 12, r = idx & 4095;
            int a = r >> 4, v = r & 15;
            float4 xv = *(const float4*)(xb + idx);
            float* dst = As_f + (size_t)(g * 16 + v) * (PA4 * 4) + a;
            dst[0 * PA4 * 4] = xv.x;
            dst[1 * PA4 * 4] = xv.y;
            dst[2 * PA4 * 4] = xv.z;
            dst[3 * PA4 * 4] = xv.w;
        }
    }
    // ---- stage ||e||^2
    for (int i = tid; i < VOCAB; i += BLK) se_s[i] = g_se[i];

    cp_wait0();
    __syncthreads();

    // ---- ||z||^2 partials from smem A (exact-product compensated fp32)
    {
        int m = tid & 63, seg = tid >> 6;
        const float4* Af = (const float4*)(smem_raw + A_OFF);
        float s = 0.0f, c = 0.0f;
        #pragma unroll 4
        for (int i = 0; i < 16; ++i) {
            float4 z = Af[m * PA4 + seg * 16 + i];
            sq_acc(z.x, s, c); sq_acc(z.y, s, c);
            sq_acc(z.z, s, c); sq_acc(z.w, s, c);
        }
        scr[seg * 128 + 2 * m]     = s;
        scr[seg * 128 + 2 * m + 1] = c;
    }
    __syncthreads();
    if (tid < M_TILE) {
        double tot = 0.0;
        #pragma unroll
        for (int seg = 0; seg < 4; ++seg) {
            tot += (double)scr[seg * 128 + 2 * tid];
            tot += (double)scr[seg * 128 + 2 * tid + 1];
        }
        szf[tid] = (float)tot;
    }
    __syncthreads();

    // ---- main loop: 8 vocab tiles x 8 K-chunks
    ull acc[8][4];
    #pragma unroll
    for (int i = 0; i < 8; ++i)
        #pragma unroll
        for (int j = 0; j < 4; ++j) acc[i][j] = 0ull;

    float bestD[8]; int bestN[8];
    #pragma unroll
    for (int i = 0; i < 8; ++i) { bestD[i] = __int_as_float(0x7f800000); bestN[i] = 0; }

    int buf = 0;
    for (int s = 0; s < 64; ++s) {
        const int t = s >> 3, c = s & 7;
        // prefetch next chunk into other buffer via cp.async (overlaps compute below)
        if (s + 1 < 64) {
            const int tn = (s + 1) >> 3, cn = (s + 1) & 7;
            const float* src = emb + (size_t)(tn * N_TILE + nr) * K_DIM + cn * 32 + kq * 4;
            const uint32_t dbase = sb + B_OFF + (buf ^ 1) * B_TILE_BYTES;
            #pragma unroll
            for (int r = 0; r < 4; ++r)
                cpa16(dbase + ((nr + 32 * r) * PB4 + kq) * 16, src + (size_t)r * 32 * K_DIM);
            cp_commit();
        }
        // compute current chunk: 8 float4-q steps (k = c*32 .. c*32+31)
        {
            const ulonglong2* Ab = (const ulonglong2*)(smem_raw + A_OFF);
            const ulonglong2* Bb = (const ulonglong2*)(smem_raw + B_OFF + buf * B_TILE_BYTES);
            #pragma unroll
            for (int qq = 0; qq < 8; ++qq) {
                ulonglong2 bv[4];
                #pragma unroll
                for (int j = 0; j < 4; ++j) bv[j] = Bb[(tx + 32 * j) * PB4 + qq];
                #pragma unroll
                for (int h = 0; h < 2; ++h) {
                    ulonglong2 av[4];
                    #pragma unroll
                    for (int ii = 0; ii < 4; ++ii)
                        av[ii] = Ab[(mb + h * 4 + ii) * PA4 + c * 8 + qq];
                    #pragma unroll
                    for (int ii = 0; ii < 4; ++ii)
                        #pragma unroll
                        for (int j = 0; j < 4; ++j) {
                            fma2(acc[h * 4 + ii][j], av[ii].x, bv[j].x);
                            fma2(acc[h * 4 + ii][j], av[ii].y, bv[j].y);
                        }
                }
            }
        }
        // end of vocab tile: fold into running argmin (exact ref rounding chain)
        if (c == 7) {
            const int n0 = t * N_TILE;
            #pragma unroll
            for (int i = 0; i < 8; ++i) {
                float szv = szf[mb + i];
                #pragma unroll
                for (int j = 0; j < 4; ++j) {
                    ull a = acc[i][j];
                    float dot = __fadd_rn(__uint_as_float((unsigned)a),
                                          __uint_as_float((unsigned)(a >> 32)));
                    int n = n0 + tx + 32 * j;
                    float tv = __fadd_rn(szv, se_s[n]);   // fl(sz + se)
                    float dist = fmaf(-2.0f, dot, tv);    // == fl(t - fl(2*dot)), *2 exact
                    if (dist < bestD[i]) { bestD[i] = dist; bestN[i] = n; }
                    acc[i][j] = 0ull;
                }
            }
        }
        cp_wait0();
        __syncthreads();
        buf ^= 1;
    }

    // ---- warp-wide argmin (32 lanes = distinct n), tie -> lowest index
    #pragma unroll
    for (int i = 0; i < 8; ++i) {
        float d = bestD[i]; int n = bestN[i];
        #pragma unroll
        for (int off = 16; off; off >>= 1) {
            float d2 = __shfl_xor_sync(0xffffffffu, d, off);
            int   n2 = __shfl_xor_sync(0xffffffffu, n, off);
            if (d2 < d || (d2 == d && n2 < n)) { d = d2; n = n2; }
        }
        if (tx == 0) tok_s[mb + i] = n;
    }
    __syncthreads();

    // ---- outputs: z_q | decoder_input | tokens (as float), guarded by out_size
    float* out_zq  = out;
    float* out_dec = out + (size_t)N_Q * K_DIM;
    float* out_tok = out + (size_t)2 * N_Q * K_DIM;
    const long long need_dec = 2LL * N_Q * K_DIM;
    const bool wd = (long long)out_size >= need_dec;
    const bool wt = (long long)out_size >= need_dec + N_Q;

    if (wt && tid < M_TILE) out_tok[m0 + tid] = (float)tok_s[tid];

    const int bl0 = blockIdx.x * 4;
    #pragma unroll
    for (int g = 0; g < 4; ++g) {
        const float* xr = x + (size_t)(bl0 + g) * AV;
        float* zr = out_zq  + (size_t)(bl0 + g) * AV;
        float* dr = out_dec + (size_t)(bl0 + g) * AV;
        for (int idx = tid * 4; idx < AV; idx += BLK * 4) {
            int a = idx >> 4, v0 = idx & 15;
            float4 xv = *(const float4*)(xr + idx);
            float4 q;
            q.x = emb[(size_t)tok_s[g * 16 + v0 + 0] * K_DIM + a];
            q.y = emb[(size_t)tok_s[g * 16 + v0 + 1] * K_DIM + a];
            q.z = emb[(size_t)tok_s[g * 16 + v0 + 2] * K_DIM + a];
            q.w = emb[(size_t)tok_s[g * 16 + v0 + 3] * K_DIM + a];
            *(float4*)(zr + idx) = q;
            if (wd) {
                float4 dv;
                dv.x = xv.x + (q.x - xv.x);
                dv.y = xv.y + (q.y - xv.y);
                dv.z = xv.z + (q.z - xv.z);
                dv.w = xv.w + (q.w - xv.w);
                *(float4*)(dr + idx) = dv;
            }
        }
    }
}

extern "C" void kernel_launch(void* const* d_in, const int* in_sizes, int n_in,
                              void* d_out, int out_size) {
    const float* x   = (const float*)d_in[0];
    const float* emb = (const float*)d_in[1];
    float* out = (float*)d_out;
    (void)in_sizes; (void)n_in;

    cudaFuncSetAttribute(vq_kernel, cudaFuncAttributeMaxDynamicSharedMemorySize, SMEM_BYTES);

    prep_se<<<(VOCAB + 255) / 256, 256>>>(emb);
    vq_kernel<<<N_Q / M_TILE, BLK, SMEM_BYTES>>>(x, emb, out, out_size);
}

// round 4
// speedup vs baseline: 1.2221x; 1.1590x over previous
#include <cuda_runtime.h>
#include <cstdint>

#define BLK     256
#define M_TILE  64
#define N_TILE  128
#define K_DIM   256
#define VOCAB   1024
#define N_Q     32768
#define AV      4096
#define PA      260         // A pitch in floats (256 + 4)
#define PBF     128         // B pitch in floats (row = 512B)

#define A_OFF        0
#define A_BYTES      (M_TILE * PA * 4)            // 66560
#define B_OFF        A_BYTES
#define B_TILE_BYTES (32 * PBF * 4)               // 16384 per buffer
#define SE_OFF       (B_OFF + 2 * B_TILE_BYTES)   // 99328
#define SCR_OFF      (SE_OFF + VOCAB * 4)         // 103424
#define SZF_OFF      (SCR_OFF + 2048)             // 105472
#define TOK_OFF      (SZF_OFF + 256)              // 105728
#define SMEM_BYTES   (TOK_OFF + 256)              // 105984

typedef unsigned long long ull;

__device__ float g_se[VOCAB];
__device__ float g_ebT[K_DIM * VOCAB];   // emb transposed: [k][n]

// ---------------- prep: ||e||^2 per vocab row ----------------
__global__ void prep_se(const float* __restrict__ emb) {
    int n = blockIdx.x * blockDim.x + threadIdx.x;
    if (n < VOCAB) {
        const float4* p = (const float4*)(emb + (size_t)n * K_DIM);
        double s = 0.0;
        #pragma unroll 8
        for (int q = 0; q < K_DIM / 4; ++q) {
            float4 e = p[q];
            s += (double)e.x * e.x + (double)e.y * e.y + (double)e.z * e.z + (double)e.w * e.w;
        }
        g_se[n] = (float)s;
    }
}

// ---------------- prep: transpose emb [n][k] -> g_ebT [k][n] ----------------
__global__ void prep_transpose(const float* __restrict__ emb) {
    __shared__ float t[32][33];
    const int tx = threadIdx.x, ty = threadIdx.y;           // (32, 8)
    const int n0 = blockIdx.x * 32, k0 = blockIdx.y * 32;
    #pragma unroll
    for (int r = 0; r < 4; ++r)
        t[ty + 8 * r][tx] = emb[(size_t)(n0 + ty + 8 * r) * K_DIM + k0 + tx];
    __syncthreads();
    #pragma unroll
    for (int r = 0; r < 4; ++r)
        g_ebT[(size_t)(k0 + ty + 8 * r) * VOCAB + n0 + tx] = t[tx][ty + 8 * r];
}

// packed fp32x2 FMA (Blackwell FFMA2)
__device__ __forceinline__ void fma2(ull& d, ull a, ull b) {
    asm("fma.rn.f32x2 %0, %1, %2, %0;" : "+l"(d) : "l"(a), "l"(b));
}
// replicate scalar into both halves of a packed f32x2
__device__ __forceinline__ ull rep2(float a) {
    ull r; asm("mov.b64 %0, {%1, %1};" : "=l"(r) : "f"(a)); return r;
}
// cp.async 16B gmem->smem
__device__ __forceinline__ void cpa16(uint32_t dst, const void* src) {
    asm volatile("cp.async.cg.shared.global [%0], [%1], 16;" :: "r"(dst), "l"(src));
}
__device__ __forceinline__ void cp_commit() { asm volatile("cp.async.commit_group;"); }
__device__ __forceinline__ void cp_wait0()  { asm volatile("cp.async.wait_group 0;" ::: "memory"); }

__device__ __forceinline__ uint32_t smem_u32(const void* p) {
    uint32_t a;
    asm("{ .reg .u64 t; cvta.to.shared.u64 t, %1; cvt.u32.u64 %0, t; }" : "=r"(a) : "l"(p));
    return a;
}

// exact-product compensated accumulate: (s,c) += z*z
__device__ __forceinline__ void sq_acc(float z, float& s, float& c) {
    float p = __fmul_rn(z, z);
    float e = fmaf(z, z, -p);
    float t = __fadd_rn(s, p);
    float bb = __fsub_rn(t, s);
    float err = __fadd_rn(__fsub_rn(s, __fsub_rn(t, bb)), __fsub_rn(p, bb));
    s = t;
    c = __fadd_rn(c, __fadd_rn(err, e));
}

extern __shared__ unsigned char smem_raw[];

__global__ void __launch_bounds__(BLK, 2)
vq_kernel(const float* __restrict__ x, const float* __restrict__ emb,
          float* __restrict__ out, int out_size) {
    float*  As_f  = (float*)(smem_raw + A_OFF);
    float*  se_s  = (float*)(smem_raw + SE_OFF);
    float*  scr   = (float*)(smem_raw + SCR_OFF);
    float*  szf   = (float*)(smem_raw + SZF_OFF);
    int*    tok_s = (int*)(smem_raw + TOK_OFF);
    const uint32_t sb = smem_u32(smem_raw);

    const int tid = threadIdx.x;
    const int tx = tid & 31;           // n-lane: owns n = 4*tx .. 4*tx+3 within tile
    const int mb = (tid >> 5) * 8;     // this warp's 8 m rows
    const int m0 = blockIdx.x * M_TILE;

    // B prefetch mapping: row pkk = tid>>3 (0..31); pq = tid&7 selects 16B chunk
    // thread copies chunks c = pq + 8j (j=0..3): src float off pq*4 + j*32,
    // dst byte off pkk*512 + pq*16 + j*128.
    const int pkk = tid >> 3, pq = tid & 7;

    // ---- issue cp.async for stage 0 (tile 0, chunk 0) into buffer 0
    {
        const float* src = g_ebT + (size_t)pkk * VOCAB + pq * 4;
        const uint32_t dst = sb + B_OFF + pkk * (PBF * 4) + pq * 16;
        #pragma unroll
        for (int j = 0; j < 4; ++j)
            cpa16(dst + j * 128, src + j * 32);
        cp_commit();
    }

    // ---- load A tile: 4 bl-rows of x, scatter into [m][k] layout (pitch PA floats)
    {
        const float* xb = x + (size_t)(blockIdx.x * 4) * AV;
        #pragma unroll
        for (int it = 0; it < 16; ++it) {
            int idx = tid * 4 + it * (BLK * 4);
            int g = idx >> 12, r = idx & 4095;
            int a = r >> 4, v = r & 15;
            float4 xv = *(const float4*)(xb + idx);
            float* dst = As_f + (size_t)(g * 16 + v) * PA + a;
            dst[0] = xv.x;          // xv.x..w are v..v+3, same a
            dst[1 * PA] = xv.y;
            dst[2 * PA] = xv.z;
            dst[3 * PA] = xv.w;
        }
    }
    // ---- stage ||e||^2
    for (int i = tid; i < VOCAB; i += BLK) se_s[i] = g_se[i];

    cp_wait0();
    __syncthreads();

    // ---- ||z||^2 partials from smem A (exact-product compensated fp32)
    {
        int m = tid & 63, seg = tid >> 6;
        float s = 0.0f, c = 0.0f;
        const float* Ar = As_f + (size_t)m * PA + seg * 64;
        #pragma unroll 4
        for (int i = 0; i < 16; ++i) {
            float4 z = *(const float4*)(Ar + i * 4);
            sq_acc(z.x, s, c); sq_acc(z.y, s, c);
            sq_acc(z.z, s, c); sq_acc(z.w, s, c);
        }
        scr[seg * 128 + 2 * m]     = s;
        scr[seg * 128 + 2 * m + 1] = c;
    }
    __syncthreads();
    if (tid < M_TILE) {
        double tot = 0.0;
        #pragma unroll
        for (int seg = 0; seg < 4; ++seg) {
            tot += (double)scr[seg * 128 + 2 * tid];
            tot += (double)scr[seg * 128 + 2 * tid + 1];
        }
        szf[tid] = (float)tot;
    }
    __syncthreads();

    // ---- main loop: 8 vocab tiles x 8 K-chunks of 32k
    ull acc[8][2];                 // [m][n-pair]: .x/.y are adjacent n dots
    #pragma unroll
    for (int i = 0; i < 8; ++i) { acc[i][0] = 0ull; acc[i][1] = 0ull; }

    float bestD[8]; int bestN[8];
    #pragma unroll
    for (int i = 0; i < 8; ++i) { bestD[i] = __int_as_float(0x7f800000); bestN[i] = 0; }

    int buf = 0;
    for (int s = 0; s < 64; ++s) {
        const int t = s >> 3, c = s & 7;
        // prefetch next chunk into other buffer
        if (s + 1 < 64) {
            const int tn = (s + 1) >> 3, cn = (s + 1) & 7;
            const float* src = g_ebT + (size_t)(cn * 32 + pkk) * VOCAB + tn * N_TILE + pq * 4;
            const uint32_t dst = sb + B_OFF + (buf ^ 1) * B_TILE_BYTES + pkk * (PBF * 4) + pq * 16;
            #pragma unroll
            for (int j = 0; j < 4; ++j)
                cpa16(dst + j * 128, src + j * 32);
            cp_commit();
        }
        // compute current chunk: k = c*32 .. c*32+31
        {
            const unsigned char* Bbuf = smem_raw + B_OFF + buf * B_TILE_BYTES;
            const float* Abase = As_f + (size_t)mb * PA + c * 32;
            #pragma unroll
            for (int c4 = 0; c4 < 8; ++c4) {
                float4 av4[8];
                #pragma unroll
                for (int ii = 0; ii < 8; ++ii)
                    av4[ii] = *(const float4*)(Abase + (size_t)ii * PA + c4 * 4);
                #pragma unroll
                for (int kk = 0; kk < 4; ++kk) {
                    ulonglong2 bv = ((const ulonglong2*)(Bbuf + (c4 * 4 + kk) * (PBF * 4)))[tx];
                    #pragma unroll
                    for (int ii = 0; ii < 8; ++ii) {
                        float a = (kk == 0) ? av4[ii].x : (kk == 1) ? av4[ii].y
                                : (kk == 2) ? av4[ii].z : av4[ii].w;
                        ull ar = rep2(a);
                        fma2(acc[ii][0], ar, bv.x);
                        fma2(acc[ii][1], ar, bv.y);
                    }
                }
            }
        }
        // end of vocab tile: fold into running argmin (exact ref rounding chain)
        if (c == 7) {
            const int n0 = t * N_TILE + 4 * tx;
            #pragma unroll
            for (int i = 0; i < 8; ++i) {
                float szv = szf[mb + i];
                #pragma unroll
                for (int j = 0; j < 2; ++j) {
                    ull a = acc[i][j];
                    #pragma unroll
                    for (int h = 0; h < 2; ++h) {
                        float dot = __uint_as_float((unsigned)(h ? (a >> 32) : a));
                        int n = n0 + 2 * j + h;
                        float tv = __fadd_rn(szv, se_s[n]);   // fl(sz + se)
                        float dist = fmaf(-2.0f, dot, tv);    // == fl(t - fl(2*dot))
                        if (dist < bestD[i]) { bestD[i] = dist; bestN[i] = n; }
                    }
                    acc[i][j] = 0ull;
                }
            }
        }
        cp_wait0();
        __syncthreads();
        buf ^= 1;
    }

    // ---- warp-wide argmin (lanes hold disjoint n sets), tie -> lowest index
    #pragma unroll
    for (int i = 0; i < 8; ++i) {
        float d = bestD[i]; int n = bestN[i];
        #pragma unroll
        for (int off = 16; off; off >>= 1) {
            float d2 = __shfl_xor_sync(0xffffffffu, d, off);
            int   n2 = __shfl_xor_sync(0xffffffffu, n, off);
            if (d2 < d || (d2 == d && n2 < n)) { d = d2; n = n2; }
        }
        if (tx == 0) tok_s[mb + i] = n;
    }
    __syncthreads();

    // ---- outputs: z_q | decoder_input | tokens (as float), guarded by out_size
    float* out_zq  = out;
    float* out_dec = out + (size_t)N_Q * K_DIM;
    float* out_tok = out + (size_t)2 * N_Q * K_DIM;
    const long long need_dec = 2LL * N_Q * K_DIM;
    const bool wd = (long long)out_size >= need_dec;
    const bool wt = (long long)out_size >= need_dec + N_Q;

    if (wt && tid < M_TILE) out_tok[m0 + tid] = (float)tok_s[tid];

    const int bl0 = blockIdx.x * 4;
    #pragma unroll
    for (int g = 0; g < 4; ++g) {
        const float* xr = x + (size_t)(bl0 + g) * AV;
        float* zr = out_zq  + (size_t)(bl0 + g) * AV;
        float* dr = out_dec + (size_t)(bl0 + g) * AV;
        for (int idx = tid * 4; idx < AV; idx += BLK * 4) {
            int a = idx >> 4, v0 = idx & 15;
            float4 xv = *(const float4*)(xr + idx);
            float4 q;
            q.x = emb[(size_t)tok_s[g * 16 + v0 + 0] * K_DIM + a];
            q.y = emb[(size_t)tok_s[g * 16 + v0 + 1] * K_DIM + a];
            q.z = emb[(size_t)tok_s[g * 16 + v0 + 2] * K_DIM + a];
            q.w = emb[(size_t)tok_s[g * 16 + v0 + 3] * K_DIM + a];
            *(float4*)(zr + idx) = q;
            if (wd) {
                float4 dv;
                dv.x = xv.x + (q.x - xv.x);
                dv.y = xv.y + (q.y - xv.y);
                dv.z = xv.z + (q.z - xv.z);
                dv.w = xv.w + (q.w - xv.w);
                *(float4*)(dr + idx) = dv;
            }
        }
    }
}

extern "C" void kernel_launch(void* const* d_in, const int* in_sizes, int n_in,
                              void* d_out, int out_size) {
    const float* x   = (const float*)d_in[0];
    const float* emb = (const float*)d_in[1];
    float* out = (float*)d_out;
    (void)in_sizes; (void)n_in;

    cudaFuncSetAttribute(vq_kernel, cudaFuncAttributeMaxDynamicSharedMemorySize, SMEM_BYTES);

    prep_se<<<(VOCAB + 255) / 256, 256>>>(emb);
    prep_transpose<<<dim3(VOCAB / 32, K_DIM / 32), dim3(32, 8)>>>(emb);
    vq_kernel<<<N_Q / M_TILE, BLK, SMEM_BYTES>>>(x, emb, out, out_size);
}

// round 5
// speedup vs baseline: 1.4369x; 1.1758x over previous
#include <cuda_runtime.h>
#include <cstdint>

#define BLK     256
#define M_TILE  64
#define N_TILE  128
#define K_DIM   256
#define VOCAB   1024
#define N_Q     32768
#define AV      4096
#define PAM     68          // A pitch in floats: [k][m], row = 64 m + 4 pad (272B, 16B-aligned)
#define PBF     128         // B pitch in floats (row = 512B)

#define A_OFF        0
#define A_BYTES      (K_DIM * PAM * 4)            // 69632
#define B_OFF        A_BYTES
#define B_TILE_BYTES (32 * PBF * 4)               // 16384 per buffer
#define SE_OFF       (B_OFF + 2 * B_TILE_BYTES)   // 102400
#define SCR_OFF      (SE_OFF + VOCAB * 4)         // 106496
#define SZF_OFF      (SCR_OFF + 2048)             // 108544
#define TOK_OFF      (SZF_OFF + 256)              // 108800
#define SMEM_BYTES   (TOK_OFF + 256)              // 109056

typedef unsigned long long ull;

__device__ float g_se[VOCAB];
__device__ float g_ebT[K_DIM * VOCAB];   // emb transposed: [k][n]

// ---------------- prep: ||e||^2, one warp per vocab row ----------------
__global__ void prep_se(const float* __restrict__ emb) {
    int w    = (blockIdx.x * blockDim.x + threadIdx.x) >> 5;
    int lane = threadIdx.x & 31;
    if (w >= VOCAB) return;
    const float4* p = (const float4*)(emb + (size_t)w * K_DIM);
    float4 e0 = p[lane], e1 = p[lane + 32];
    double s = (double)e0.x * e0.x + (double)e0.y * e0.y
             + (double)e0.z * e0.z + (double)e0.w * e0.w
             + (double)e1.x * e1.x + (double)e1.y * e1.y
             + (double)e1.z * e1.z + (double)e1.w * e1.w;
    #pragma unroll
    for (int off = 16; off; off >>= 1)
        s += __shfl_down_sync(0xffffffffu, s, off);
    if (lane == 0) g_se[w] = (float)s;
}

// ---------------- prep: transpose emb [n][k] -> g_ebT [k][n] ----------------
__global__ void prep_transpose(const float* __restrict__ emb) {
    __shared__ float t[32][33];
    const int tx = threadIdx.x, ty = threadIdx.y;           // (32, 8)
    const int n0 = blockIdx.x * 32, k0 = blockIdx.y * 32;
    #pragma unroll
    for (int r = 0; r < 4; ++r)
        t[ty + 8 * r][tx] = emb[(size_t)(n0 + ty + 8 * r) * K_DIM + k0 + tx];
    __syncthreads();
    #pragma unroll
    for (int r = 0; r < 4; ++r)
        g_ebT[(size_t)(k0 + ty + 8 * r) * VOCAB + n0 + tx] = t[tx][ty + 8 * r];
}

// packed fp32x2 FMA (Blackwell FFMA2)
__device__ __forceinline__ void fma2(ull& d, ull a, ull b) {
    asm("fma.rn.f32x2 %0, %1, %2, %0;" : "+l"(d) : "l"(a), "l"(b));
}
// replicate scalar into both halves of a packed f32x2
__device__ __forceinline__ ull rep2(float a) {
    ull r; asm("mov.b64 %0, {%1, %1};" : "=l"(r) : "f"(a)); return r;
}
// cp.async 16B gmem->smem
__device__ __forceinline__ void cpa16(uint32_t dst, const void* src) {
    asm volatile("cp.async.cg.shared.global [%0], [%1], 16;" :: "r"(dst), "l"(src));
}
__device__ __forceinline__ void cp_commit() { asm volatile("cp.async.commit_group;"); }
__device__ __forceinline__ void cp_wait0()  { asm volatile("cp.async.wait_group 0;" ::: "memory"); }

__device__ __forceinline__ uint32_t smem_u32(const void* p) {
    uint32_t a;
    asm("{ .reg .u64 t; cvta.to.shared.u64 t, %1; cvt.u32.u64 %0, t; }" : "=r"(a) : "l"(p));
    return a;
}

// exact-product compensated accumulate: (s,c) += z*z
__device__ __forceinline__ void sq_acc(float z, float& s, float& c) {
    float p = __fmul_rn(z, z);
    float e = fmaf(z, z, -p);
    float t = __fadd_rn(s, p);
    float bb = __fsub_rn(t, s);
    float err = __fadd_rn(__fsub_rn(s, __fsub_rn(t, bb)), __fsub_rn(p, bb));
    s = t;
    c = __fadd_rn(c, __fadd_rn(err, e));
}

extern __shared__ unsigned char smem_raw[];

__global__ void __launch_bounds__(BLK, 2)
vq_kernel(const float* __restrict__ x, const float* __restrict__ emb,
          float* __restrict__ out, int out_size) {
    float*  As_f  = (float*)(smem_raw + A_OFF);     // [k][m], pitch PAM
    float*  se_s  = (float*)(smem_raw + SE_OFF);
    float*  scr   = (float*)(smem_raw + SCR_OFF);
    float*  szf   = (float*)(smem_raw + SZF_OFF);
    int*    tok_s = (int*)(smem_raw + TOK_OFF);
    const uint32_t sb = smem_u32(smem_raw);

    const int tid = threadIdx.x;
    const int tx = tid & 31;           // n-lane: owns n = 4*tx .. 4*tx+3 within tile
    const int mb = (tid >> 5) * 8;     // this warp's 8 m rows
    const int m0 = blockIdx.x * M_TILE;

    // B prefetch mapping (VALIDATED in R4 — unchanged): row pkk, 16B chunk pq + 8j
    const int pkk = tid >> 3, pq = tid & 7;

    // ---- issue cp.async for stage 0 (tile 0, chunk 0) into buffer 0
    {
        const float* src = g_ebT + (size_t)pkk * VOCAB + pq * 4;
        const uint32_t dst = sb + B_OFF + pkk * (PBF * 4) + pq * 16;
        #pragma unroll
        for (int j = 0; j < 4; ++j)
            cpa16(dst + j * 128, src + j * 32);
        cp_commit();
    }

    // ---- load A tile into [k][m]: As[a][g*16+v] = x[bl0+g][a*16+v]; STS.128 (m contig)
    {
        const float* xb = x + (size_t)(blockIdx.x * 4) * AV;
        #pragma unroll
        for (int it = 0; it < 16; ++it) {
            int idx = tid * 4 + it * (BLK * 4);
            int g = idx >> 12, r = idx & 4095;
            int a = r >> 4, v = r & 15;          // v multiple of 4
            float4 xv = *(const float4*)(xb + idx);
            *(float4*)(As_f + (size_t)a * PAM + g * 16 + v) = xv;
        }
    }
    // ---- stage ||e||^2
    for (int i = tid; i < VOCAB; i += BLK) se_s[i] = g_se[i];

    cp_wait0();
    __syncthreads();

    // ---- ||z||^2 partials from smem A[k][m] (exact-product compensated fp32)
    {
        int m = tid & 63, seg = tid >> 6;
        float s = 0.0f, c = 0.0f;
        const float* Ar = As_f + m + (size_t)(seg * 64) * PAM;
        #pragma unroll 8
        for (int i = 0; i < 64; ++i)
            sq_acc(Ar[(size_t)i * PAM], s, c);
        scr[seg * 128 + 2 * m]     = s;
        scr[seg * 128 + 2 * m + 1] = c;
    }
    __syncthreads();
    if (tid < M_TILE) {
        double tot = 0.0;
        #pragma unroll
        for (int seg = 0; seg < 4; ++seg) {
            tot += (double)scr[seg * 128 + 2 * tid];
            tot += (double)scr[seg * 128 + 2 * tid + 1];
        }
        szf[tid] = (float)tot;
    }
    __syncthreads();

    // ---- main loop: 8 vocab tiles x 8 K-chunks of 32k; m-packed accumulators
    ull acc[4][4];                 // [m-pair p][n j]: low = m=mb+2p, high = m=mb+2p+1
    #pragma unroll
    for (int p = 0; p < 4; ++p)
        #pragma unroll
        for (int j = 0; j < 4; ++j) acc[p][j] = 0ull;

    float bestD[8]; int bestN[8];
    #pragma unroll
    for (int i = 0; i < 8; ++i) { bestD[i] = __int_as_float(0x7f800000); bestN[i] = 0; }

    int buf = 0;
    for (int s = 0; s < 64; ++s) {
        const int t = s >> 3, c = s & 7;
        // prefetch next chunk into other buffer (addressing unchanged from R4)
        if (s + 1 < 64) {
            const int tn = (s + 1) >> 3, cn = (s + 1) & 7;
            const float* src = g_ebT + (size_t)(cn * 32 + pkk) * VOCAB + tn * N_TILE + pq * 4;
            const uint32_t dst = sb + B_OFF + (buf ^ 1) * B_TILE_BYTES + pkk * (PBF * 4) + pq * 16;
            #pragma unroll
            for (int j = 0; j < 4; ++j)
                cpa16(dst + j * 128, src + j * 32);
            cp_commit();
        }
        // compute current chunk: k = c*32 .. c*32+31
        {
            const float* Bbuf = (const float*)(smem_raw + B_OFF + buf * B_TILE_BYTES);
            const float* Ak   = As_f + (size_t)(c * 32) * PAM + mb;
            #pragma unroll 8
            for (int k = 0; k < 32; ++k) {
                // A: two uniform LDS.128 -> 4 ready-packed m-pairs
                ulonglong2 a01 = *(const ulonglong2*)(Ak + (size_t)k * PAM);
                ulonglong2 a23 = *(const ulonglong2*)(Ak + (size_t)k * PAM + 4);
                // B: 4 n values for this lane
                float4 b4 = *(const float4*)(Bbuf + (size_t)k * PBF + tx * 4);
                ull b0 = rep2(b4.x), b1 = rep2(b4.y), b2 = rep2(b4.z), b3 = rep2(b4.w);
                fma2(acc[0][0], a01.x, b0); fma2(acc[0][1], a01.x, b1);
                fma2(acc[0][2], a01.x, b2); fma2(acc[0][3], a01.x, b3);
                fma2(acc[1][0], a01.y, b0); fma2(acc[1][1], a01.y, b1);
                fma2(acc[1][2], a01.y, b2); fma2(acc[1][3], a01.y, b3);
                fma2(acc[2][0], a23.x, b0); fma2(acc[2][1], a23.x, b1);
                fma2(acc[2][2], a23.x, b2); fma2(acc[2][3], a23.x, b3);
                fma2(acc[3][0], a23.y, b0); fma2(acc[3][1], a23.y, b1);
                fma2(acc[3][2], a23.y, b2); fma2(acc[3][3], a23.y, b3);
            }
        }
        // end of vocab tile: fold into running argmin (exact ref rounding chain)
        if (c == 7) {
            const int n0 = t * N_TILE + 4 * tx;
            #pragma unroll
            for (int p = 0; p < 4; ++p) {
                #pragma unroll
                for (int j = 0; j < 4; ++j) {
                    ull a = acc[p][j];
                    int n = n0 + j;
                    float sen = se_s[n];
                    #pragma unroll
                    for (int h = 0; h < 2; ++h) {
                        float dot = __uint_as_float((unsigned)(h ? (a >> 32) : a));
                        int i = 2 * p + h;                     // m = mb + i
                        float tv = __fadd_rn(szf[mb + i], sen); // fl(sz + se)
                        float dist = fmaf(-2.0f, dot, tv);      // == fl(t - fl(2*dot))
                        if (dist < bestD[i]) { bestD[i] = dist; bestN[i] = n; }
                    }
                    acc[p][j] = 0ull;
                }
            }
        }
        cp_wait0();
        __syncthreads();
        buf ^= 1;
    }

    // ---- warp-wide argmin (lanes hold disjoint n sets), tie -> lowest index
    #pragma unroll
    for (int i = 0; i < 8; ++i) {
        float d = bestD[i]; int n = bestN[i];
        #pragma unroll
        for (int off = 16; off; off >>= 1) {
            float d2 = __shfl_xor_sync(0xffffffffu, d, off);
            int   n2 = __shfl_xor_sync(0xffffffffu, n, off);
            if (d2 < d || (d2 == d && n2 < n)) { d = d2; n = n2; }
        }
        if (tx == 0) tok_s[mb + i] = n;
    }
    __syncthreads();

    // ---- outputs: z_q | decoder_input | tokens (as float), guarded by out_size
    float* out_zq  = out;
    float* out_dec = out + (size_t)N_Q * K_DIM;
    float* out_tok = out + (size_t)2 * N_Q * K_DIM;
    const long long need_dec = 2LL * N_Q * K_DIM;
    const bool wd = (long long)out_size >= need_dec;
    const bool wt = (long long)out_size >= need_dec + N_Q;

    if (wt && tid < M_TILE) out_tok[m0 + tid] = (float)tok_s[tid];

    const int bl0 = blockIdx.x * 4;
    #pragma unroll
    for (int g = 0; g < 4; ++g) {
        const float* xr = x + (size_t)(bl0 + g) * AV;
        float* zr = out_zq  + (size_t)(bl0 + g) * AV;
        float* dr = out_dec + (size_t)(bl0 + g) * AV;
        for (int idx = tid * 4; idx < AV; idx += BLK * 4) {
            int a = idx >> 4, v0 = idx & 15;
            float4 xv = *(const float4*)(xr + idx);
            float4 q;
            q.x = emb[(size_t)tok_s[g * 16 + v0 + 0] * K_DIM + a];
            q.y = emb[(size_t)tok_s[g * 16 + v0 + 1] * K_DIM + a];
            q.z = emb[(size_t)tok_s[g * 16 + v0 + 2] * K_DIM + a];
            q.w = emb[(size_t)tok_s[g * 16 + v0 + 3] * K_DIM + a];
            *(float4*)(zr + idx) = q;
            if (wd) {
                float4 dv;
                dv.x = xv.x + (q.x - xv.x);
                dv.y = xv.y + (q.y - xv.y);
                dv.z = xv.z + (q.z - xv.z);
                dv.w = xv.w + (q.w - xv.w);
                *(float4*)(dr + idx) = dv;
            }
        }
    }
}

extern "C" void kernel_launch(void* const* d_in, const int* in_sizes, int n_in,
                              void* d_out, int out_size) {
    const float* x   = (const float*)d_in[0];
    const float* emb = (const float*)d_in[1];
    float* out = (float*)d_out;
    (void)in_sizes; (void)n_in;

    cudaFuncSetAttribute(vq_kernel, cudaFuncAttributeMaxDynamicSharedMemorySize, SMEM_BYTES);

    prep_se<<<(VOCAB * 32) / BLK, BLK>>>(emb);
    prep_transpose<<<dim3(VOCAB / 32, K_DIM / 32), dim3(32, 8)>>>(emb);
    vq_kernel<<<N_Q / M_TILE, BLK, SMEM_BYTES>>>(x, emb, out, out_size);
}

// round 7
// speedup vs baseline: 2.4762x; 1.7233x over previous
#include <cuda_runtime.h>
#include <cuda_bf16.h>
#include <cstdint>

#define BLK     256
#define M_TILE  64
#define K_DIM   256
#define VOCAB   1024
#define N_Q     32768
#define AV      4096
#define PA_B    528          // A smem row pitch bytes (512 data + 16 pad)
#define PB_B    144          // B smem row pitch bytes (128 data + 16 pad)
#define MARGIN  3.2e-4f

// ---- smem layout (bytes) ----
#define A_OFF     0
#define A_BYTES   (64 * PA_B)                 // 33792
#define B_OFF     A_BYTES
#define B_TILE_B  (128 * PB_B)                // 18432 per buffer
#define SE_OFF    (B_OFF + 2 * B_TILE_B)      // 70656
#define SZF_OFF   (SE_OFF + 4096)             // 74752
#define CMIN_OFF  (SZF_OFF + 256)             // 75008  (128 floats)
#define THR_OFF   (CMIN_OFF + 512)            // 75520  (64 floats)
#define CNT_OFF   (THR_OFF + 256)             // 75776  (64 ints)
#define CAND_OFF  (CNT_OFF + 256)             // 76032  (64*12 ints)
#define TOK_OFF   (CAND_OFF + 3072)           // 79104
#define SMEM_BYTES (TOK_OFF + 256)            // 79360

__device__ unsigned int g_xb[N_Q * 128];      // x as bf16 pairs: [m][kpair]
__device__ unsigned int g_ebB[VOCAB * 128];   // emb as bf16 pairs: [n][kpair]
__device__ float g_se[VOCAB];
__device__ float g_sz[N_Q];

// ---------------- helpers ----------------
__device__ __forceinline__ uint32_t smem_u32(const void* p) {
    uint32_t a;
    asm("{ .reg .u64 t; cvta.to.shared.u64 t, %1; cvt.u32.u64 %0, t; }" : "=r"(a) : "l"(p));
    return a;
}
__device__ __forceinline__ void cpa16(uint32_t dst, const void* src) {
    asm volatile("cp.async.cg.shared.global [%0], [%1], 16;" :: "r"(dst), "l"(src));
}
__device__ __forceinline__ void cp_commit() { asm volatile("cp.async.commit_group;"); }
__device__ __forceinline__ void cp_wait0()  { asm volatile("cp.async.wait_group 0;" ::: "memory"); }

__device__ __forceinline__ void ldsm4(uint32_t& r0, uint32_t& r1, uint32_t& r2, uint32_t& r3,
                                      uint32_t addr) {
    asm volatile("ldmatrix.sync.aligned.m8n8.x4.shared.b16 {%0,%1,%2,%3}, [%4];"
                 : "=r"(r0), "=r"(r1), "=r"(r2), "=r"(r3) : "r"(addr));
}
__device__ __forceinline__ void mma_bf16(float* d, uint32_t a0, uint32_t a1, uint32_t a2,
                                         uint32_t a3, uint32_t b0, uint32_t b1) {
    asm volatile("mma.sync.aligned.m16n8k16.row.col.f32.bf16.bf16.f32 "
                 "{%0,%1,%2,%3}, {%4,%5,%6,%7}, {%8,%9}, {%0,%1,%2,%3};"
                 : "+f"(d[0]), "+f"(d[1]), "+f"(d[2]), "+f"(d[3])
                 : "r"(a0), "r"(a1), "r"(a2), "r"(a3), "r"(b0), "r"(b1));
}

__device__ __forceinline__ unsigned pack_bf16(float x, float y) {
    return (unsigned)__bfloat16_as_ushort(__float2bfloat16(x))
         | ((unsigned)__bfloat16_as_ushort(__float2bfloat16(y)) << 16);
}

// exact-product compensated accumulate: (s,c) += z*z
__device__ __forceinline__ void sq_acc(float z, float& s, float& c) {
    float p = __fmul_rn(z, z);
    float e = fmaf(z, z, -p);
    float t = __fadd_rn(s, p);
    float bb = __fsub_rn(t, s);
    float err = __fadd_rn(__fsub_rn(s, __fsub_rn(t, bb)), __fsub_rn(p, bb));
    s = t;
    c = __fadd_rn(c, __fadd_rn(err, e));
}

__device__ __forceinline__ void top3(float* T, int* N, float v, int n) {
    if (v < T[2]) {
        if (v < T[1]) {
            T[2] = T[1]; N[2] = N[1];
            if (v < T[0]) { T[1] = T[0]; N[1] = N[0]; T[0] = v; N[0] = n; }
            else          { T[1] = v;    N[1] = n; }
        } else { T[2] = v; N[2] = n; }
    }
}

// ---------------- prep: emb -> bf16 [n][kpair] + ||e||^2 (warp/row) ----------------
__global__ void prep_eb(const float* __restrict__ emb) {
    int w = (blockIdx.x * blockDim.x + threadIdx.x) >> 5;
    int lane = threadIdx.x & 31;
    if (w >= VOCAB) return;
    const float* row = emb + (size_t)w * K_DIM;
    double s = 0.0;
    #pragma unroll
    for (int h = 0; h < 2; ++h) {
        float4 e = *(const float4*)(row + lane * 4 + h * 128);
        int col = 2 * lane + h * 64;
        g_ebB[w * 128 + col]     = pack_bf16(e.x, e.y);
        g_ebB[w * 128 + col + 1] = pack_bf16(e.z, e.w);
        s += (double)e.x * e.x + (double)e.y * e.y + (double)e.z * e.z + (double)e.w * e.w;
    }
    #pragma unroll
    for (int off = 16; off; off >>= 1)
        s += __shfl_down_sync(0xffffffffu, s, off);
    if (lane == 0) g_se[w] = (float)s;
}

// ---------------- prep: x -> bf16 [m][kpair] + ||z||^2 ----------------
__global__ void prep_x(const float* __restrict__ x) {
    __shared__ float sx[4096];
    __shared__ float scr[512];
    const int g = blockIdx.x, tid = threadIdx.x;
    const float4* xb = (const float4*)(x + (size_t)g * AV);
    #pragma unroll
    for (int it = 0; it < 4; ++it)
        *(float4*)(sx + (tid + it * 256) * 4) = xb[tid + it * 256];
    __syncthreads();
    {
        int v = tid & 15, cg = tid >> 4;
        #pragma unroll
        for (int j = 0; j < 8; ++j) {
            int c = cg * 8 + j;
            float za = sx[(2 * c) * 16 + v];
            float zb = sx[(2 * c + 1) * 16 + v];
            g_xb[(size_t)(g * 16 + v) * 128 + c] = pack_bf16(za, zb);
        }
    }
    {
        int vv = tid & 15, seg = tid >> 4;
        float s = 0.0f, cc = 0.0f;
        #pragma unroll
        for (int k = 0; k < 16; ++k)
            sq_acc(sx[(seg * 16 + k) * 16 + vv], s, cc);
        scr[(vv * 16 + seg) * 2] = s;
        scr[(vv * 16 + seg) * 2 + 1] = cc;
    }
    __syncthreads();
    if (tid < 16) {
        double tot = 0.0;
        #pragma unroll
        for (int seg = 0; seg < 16; ++seg) {
            tot += (double)scr[(tid * 16 + seg) * 2];
            tot += (double)scr[(tid * 16 + seg) * 2 + 1];
        }
        g_sz[g * 16 + tid] = (float)tot;
    }
}

extern __shared__ unsigned char smem_raw[];

// ---------------- main: coarse bf16 HMMA + exact fp32 re-rank + writeback ----------------
__global__ void __launch_bounds__(BLK)
vq_kernel(const float* __restrict__ x, const float* __restrict__ emb,
          float* __restrict__ out, int out_size) {
    float* se_s  = (float*)(smem_raw + SE_OFF);
    float* szf   = (float*)(smem_raw + SZF_OFF);
    float* cminw = (float*)(smem_raw + CMIN_OFF);
    float* thr_s = (float*)(smem_raw + THR_OFF);
    int*   cnt_s = (int*)(smem_raw + CNT_OFF);
    int*   cand_s = (int*)(smem_raw + CAND_OFF);
    int*   tok_s = (int*)(smem_raw + TOK_OFF);
    const uint32_t sb = smem_u32(smem_raw);

    const int tid = threadIdx.x;
    const int lane = tid & 31, wid = tid >> 5;
    const int mw = (wid & 3) * 16;        // warp m offset (0..48)
    const int nw = (wid >> 2) * 64;       // warp n half (0/64)
    const int gr = lane >> 2, gc = (lane & 3) * 2;
    const int m0 = blockIdx.x * M_TILE;

    // ldmatrix lane address components
    const uint32_t aAddr = sb + A_OFF
        + (uint32_t)(mw + (lane & 7) + ((lane >> 3) & 1) * 8) * PA_B
        + ((lane >> 4) & 1) * 16;
    const uint32_t bAddr = sb + B_OFF
        + (uint32_t)(nw + (lane & 7) + (lane >> 4) * 8) * PB_B
        + ((lane >> 3) & 1) * 16;

    // ---- stage 0 B prefetch into buf 0 (rows=tid>>1, 2 threads/row)
    {
        const int row = tid >> 1, half = (tid & 1) * 64;
        const char* src = (const char*)g_ebB + (size_t)row * 512 + half;
        const uint32_t dst = sb + B_OFF + row * PB_B + half;
        #pragma unroll
        for (int j = 0; j < 4; ++j) cpa16(dst + j * 16, src + j * 16);
        cp_commit();
    }
    // ---- A tile (bf16, full K) via cp.async
    {
        const int row = tid >> 2;
        const char* src = (const char*)g_xb + (size_t)(m0 + row) * 512;
        const uint32_t dst = sb + A_OFF + row * PA_B;
        #pragma unroll
        for (int j = 0; j < 8; ++j) {
            int ch = (tid & 3) + 4 * j;
            cpa16(dst + ch * 16, src + ch * 16);
        }
        cp_commit();
    }
    // ---- stage se, sz
    for (int i = tid; i < VOCAB; i += BLK) se_s[i] = g_se[i];
    if (tid < M_TILE) szf[tid] = g_sz[m0 + tid];

    // ---- coarse fold state
    float d[8][4];
    #pragma unroll
    for (int f = 0; f < 8; ++f)
        #pragma unroll
        for (int j = 0; j < 4; ++j) d[f][j] = 0.0f;
    const float INFV = __int_as_float(0x7f800000);
    float T0[3] = {INFV, INFV, INFV}, T1[3] = {INFV, INFV, INFV};
    int   N0[3] = {0, 0, 0},          N1[3] = {0, 0, 0};

    // ---- main loop: 8 n-tiles x 4 k-chunks (64k each)
    #pragma unroll 1
    for (int s = 0; s < 32; ++s) {
        cp_wait0();
        __syncthreads();
        const int t = s >> 2, c = s & 3, buf = s & 1;
        // prefetch next chunk into buf^1
        if (s + 1 < 32) {
            const int t2 = (s + 1) >> 2, c2 = (s + 1) & 3;
            const int row = tid >> 1, half = (tid & 1) * 64;
            const char* src = (const char*)g_ebB + (size_t)(t2 * 128 + row) * 512
                            + c2 * 128 + half;
            const uint32_t dst = sb + B_OFF + (buf ^ 1) * B_TILE_B + row * PB_B + half;
            #pragma unroll
            for (int j = 0; j < 4; ++j) cpa16(dst + j * 16, src + j * 16);
            cp_commit();
        }
        // compute: 4 k16 steps on buf
        #pragma unroll
        for (int kk = 0; kk < 4; ++kk) {
            uint32_t a0, a1, a2, a3;
            ldsm4(a0, a1, a2, a3, aAddr + c * 128 + kk * 32);
            #pragma unroll
            for (int fp = 0; fp < 4; ++fp) {
                uint32_t b0, b1, b2, b3;
                ldsm4(b0, b1, b2, b3, bAddr + buf * B_TILE_B + fp * (16 * PB_B) + kk * 32);
                mma_bf16(d[2 * fp],     a0, a1, a2, a3, b0, b1);
                mma_bf16(d[2 * fp + 1], a0, a1, a2, a3, b2, b3);
            }
        }
        // end of n-tile: coarse dist (se - 2*dot, no sz) + top-3 fold
        if (c == 3) {
            #pragma unroll
            for (int f = 0; f < 8; ++f) {
                const int nn = t * 128 + nw + f * 8 + gc;
                const float se0 = se_s[nn], se1 = se_s[nn + 1];
                top3(T0, N0, fmaf(-2.0f, d[f][0], se0), nn);
                top3(T0, N0, fmaf(-2.0f, d[f][1], se1), nn + 1);
                top3(T1, N1, fmaf(-2.0f, d[f][2], se0), nn);
                top3(T1, N1, fmaf(-2.0f, d[f][3], se1), nn + 1);
                d[f][0] = 0.0f; d[f][1] = 0.0f; d[f][2] = 0.0f; d[f][3] = 0.0f;
            }
        }
    }

    // ---- coarse min per m: quad-reduce best1, combine across n-halves
    {
        float v0 = T0[0], v1 = T1[0];
        #pragma unroll
        for (int off = 1; off <= 2; off <<= 1) {
            v0 = fminf(v0, __shfl_xor_sync(0xffffffffu, v0, off));
            v1 = fminf(v1, __shfl_xor_sync(0xffffffffu, v1, off));
        }
        if ((lane & 3) == 0) {
            cminw[(wid >> 2) * 64 + mw + gr]     = v0;
            cminw[(wid >> 2) * 64 + mw + gr + 8] = v1;
        }
    }
    __syncthreads();
    if (tid < M_TILE) {
        thr_s[tid] = fminf(cminw[tid], cminw[64 + tid]) + MARGIN;
        cnt_s[tid] = 0;
    }
    __syncthreads();
    // ---- append candidates within margin
    {
        const int mloc0 = mw + gr, mloc1 = mw + gr + 8;
        const float th0 = thr_s[mloc0], th1 = thr_s[mloc1];
        #pragma unroll
        for (int i = 0; i < 3; ++i) {
            if (T0[i] <= th0) {
                int pos = atomicAdd(&cnt_s[mloc0], 1);
                if (pos < 12) cand_s[mloc0 * 12 + pos] = N0[i];
            }
            if (T1[i] <= th1) {
                int pos = atomicAdd(&cnt_s[mloc1], 1);
                if (pos < 12) cand_s[mloc1 * 12 + pos] = N1[i];
            }
        }
    }
    __syncthreads();

    // ---- exact fp32 re-rank (thread per m row), ref rounding chain + index tie-break
    if (tid < M_TILE) {
        const int mg = m0 + tid;
        const float* xr = x + (size_t)(mg >> 4) * AV + (mg & 15);
        const float szm = szf[tid];
        int nc = cnt_s[tid]; if (nc > 12) nc = 12;
        float bestD = INFV; int bestN = 0x7fffffff;
        for (int i = 0; i < nc; ++i) {
            const int n = cand_s[tid * 12 + i];
            const float* er = emb + (size_t)n * K_DIM;
            float p0 = 0.f, p1 = 0.f, p2 = 0.f, p3 = 0.f;
            #pragma unroll 4
            for (int a = 0; a < K_DIM; a += 4) {
                p0 = fmaf(xr[(a + 0) * 16], er[a + 0], p0);
                p1 = fmaf(xr[(a + 1) * 16], er[a + 1], p1);
                p2 = fmaf(xr[(a + 2) * 16], er[a + 2], p2);
                p3 = fmaf(xr[(a + 3) * 16], er[a + 3], p3);
            }
            const float dot = __fadd_rn(__fadd_rn(p0, p1), __fadd_rn(p2, p3));
            const float tv = __fadd_rn(szm, se_s[n]);   // fl(sz + se)
            const float dist = fmaf(-2.0f, dot, tv);    // == fl(t - fl(2*dot))
            if (dist < bestD || (dist == bestD && n < bestN)) { bestD = dist; bestN = n; }
        }
        tok_s[tid] = bestN;
    }
    __syncthreads();

    // ---- outputs: z_q | decoder_input | tokens (as float), guarded by out_size
    float* out_zq  = out;
    float* out_dec = out + (size_t)N_Q * K_DIM;
    float* out_tok = out + (size_t)2 * N_Q * K_DIM;
    const long long need_dec = 2LL * N_Q * K_DIM;
    const bool wd = (long long)out_size >= need_dec;
    const bool wt = (long long)out_size >= need_dec + N_Q;

    if (wt && tid < M_TILE) out_tok[m0 + tid] = (float)tok_s[tid];

    const int bl0 = blockIdx.x * 4;
    #pragma unroll
    for (int g = 0; g < 4; ++g) {
        const float* xr = x + (size_t)(bl0 + g) * AV;
        float* zr = out_zq  + (size_t)(bl0 + g) * AV;
        float* dr = out_dec + (size_t)(bl0 + g) * AV;
        for (int idx = tid * 4; idx < AV; idx += BLK * 4) {
            int a = idx >> 4, v0 = idx & 15;
            float4 xv = *(const float4*)(xr + idx);
            float4 q;
            q.x = emb[(size_t)tok_s[g * 16 + v0 + 0] * K_DIM + a];
            q.y = emb[(size_t)tok_s[g * 16 + v0 + 1] * K_DIM + a];
            q.z = emb[(size_t)tok_s[g * 16 + v0 + 2] * K_DIM + a];
            q.w = emb[(size_t)tok_s[g * 16 + v0 + 3] * K_DIM + a];
            *(float4*)(zr + idx) = q;
            if (wd) {
                float4 dv;
                dv.x = xv.x + (q.x - xv.x);
                dv.y = xv.y + (q.y - xv.y);
                dv.z = xv.z + (q.z - xv.z);
                dv.w = xv.w + (q.w - xv.w);
                *(float4*)(dr + idx) = dv;
            }
        }
    }
}

extern "C" void kernel_launch(void* const* d_in, const int* in_sizes, int n_in,
                              void* d_out, int out_size) {
    const float* x   = (const float*)d_in[0];
    const float* emb = (const float*)d_in[1];
    float* out = (float*)d_out;
    (void)in_sizes; (void)n_in;

    cudaFuncSetAttribute(vq_kernel, cudaFuncAttributeMaxDynamicSharedMemorySize, SMEM_BYTES);

    prep_eb<<<(VOCAB * 32) / BLK, BLK>>>(emb);
    prep_x<<<N_Q / 16, BLK>>>(x);
    vq_kernel<<<N_Q / M_TILE, BLK, SMEM_BYTES>>>(x, emb, out, out_size);
}

// round 8
// speedup vs baseline: 2.7878x; 1.1258x over previous
#include <cuda_runtime.h>
#include <cuda_bf16.h>
#include <cstdint>

#define BLK     512
#define M_TILE  128
#define K_DIM   256
#define VOCAB   1024
#define N_Q     32768
#define AV      4096
#define PA_B    528          // A smem row pitch bytes (512 data + 16 pad)
#define PB_B    144          // B smem row pitch bytes (128 data + 16 pad)
#define MARGIN  3.2e-4f

// ---- smem layout (bytes) ----
#define A_OFF     0
#define A_BYTES   (M_TILE * PA_B)             // 67584
#define B_OFF     A_BYTES
#define B_TILE_B  (128 * PB_B)                // 18432 per buffer
#define SE_OFF    (B_OFF + 2 * B_TILE_B)      // 104448
#define SZF_OFF   (SE_OFF + 4096)             // 108544
#define CMIN_OFF  (SZF_OFF + 512)             // 109056  (256 floats)
#define THR_OFF   (CMIN_OFF + 1024)           // 110080  (128 floats)
#define CNT_OFF   (THR_OFF + 512)             // 110592  (128 ints)
#define CAND_OFF  (CNT_OFF + 512)             // 111104  (128*12 ints)
#define TOK_OFF   (CAND_OFF + 6144)           // 117248
#define SMEM_BYTES (TOK_OFF + 512)            // 117760

__device__ unsigned int g_xb[N_Q * 128];      // x as bf16 pairs: [m][kpair]
__device__ unsigned int g_ebB[VOCAB * 128];   // emb as bf16 pairs: [n][kpair]
__device__ float g_se[VOCAB];
__device__ float g_sz[N_Q];

// ---------------- helpers ----------------
__device__ __forceinline__ uint32_t smem_u32(const void* p) {
    uint32_t a;
    asm("{ .reg .u64 t; cvta.to.shared.u64 t, %1; cvt.u32.u64 %0, t; }" : "=r"(a) : "l"(p));
    return a;
}
__device__ __forceinline__ void cpa16(uint32_t dst, const void* src) {
    asm volatile("cp.async.cg.shared.global [%0], [%1], 16;" :: "r"(dst), "l"(src));
}
__device__ __forceinline__ void cp_commit() { asm volatile("cp.async.commit_group;"); }
__device__ __forceinline__ void cp_wait0()  { asm volatile("cp.async.wait_group 0;" ::: "memory"); }

__device__ __forceinline__ void ldsm4(uint32_t& r0, uint32_t& r1, uint32_t& r2, uint32_t& r3,
                                      uint32_t addr) {
    asm volatile("ldmatrix.sync.aligned.m8n8.x4.shared.b16 {%0,%1,%2,%3}, [%4];"
                 : "=r"(r0), "=r"(r1), "=r"(r2), "=r"(r3) : "r"(addr));
}
__device__ __forceinline__ void mma_bf16(float* d, uint32_t a0, uint32_t a1, uint32_t a2,
                                         uint32_t a3, uint32_t b0, uint32_t b1) {
    asm volatile("mma.sync.aligned.m16n8k16.row.col.f32.bf16.bf16.f32 "
                 "{%0,%1,%2,%3}, {%4,%5,%6,%7}, {%8,%9}, {%0,%1,%2,%3};"
                 : "+f"(d[0]), "+f"(d[1]), "+f"(d[2]), "+f"(d[3])
                 : "r"(a0), "r"(a1), "r"(a2), "r"(a3), "r"(b0), "r"(b1));
}

__device__ __forceinline__ unsigned pack_bf16(float x, float y) {
    return (unsigned)__bfloat16_as_ushort(__float2bfloat16(x))
         | ((unsigned)__bfloat16_as_ushort(__float2bfloat16(y)) << 16);
}

// exact-product compensated accumulate: (s,c) += z*z
__device__ __forceinline__ void sq_acc(float z, float& s, float& c) {
    float p = __fmul_rn(z, z);
    float e = fmaf(z, z, -p);
    float t = __fadd_rn(s, p);
    float bb = __fsub_rn(t, s);
    float err = __fadd_rn(__fsub_rn(s, __fsub_rn(t, bb)), __fsub_rn(p, bb));
    s = t;
    c = __fadd_rn(c, __fadd_rn(err, e));
}

__device__ __forceinline__ void top3(float* T, int* N, float v, int n) {
    if (v < T[2]) {
        if (v < T[1]) {
            T[2] = T[1]; N[2] = N[1];
            if (v < T[0]) { T[1] = T[0]; N[1] = N[0]; T[0] = v; N[0] = n; }
            else          { T[1] = v;    N[1] = n; }
        } else { T[2] = v; N[2] = n; }
    }
}

// ---------------- merged prep (256 threads/block) ----------------
// blocks [0, 2048): x -> bf16 [m][kpair] + ||z||^2 (block per b,l pair)
// blocks [2048, 2176): emb -> bf16 [n][kpair] + ||e||^2 (warp per row)
__global__ void prep_all(const float* __restrict__ x, const float* __restrict__ emb) {
    __shared__ float sx[4096];
    __shared__ float scr[512];
    const int tid = threadIdx.x;
    if (blockIdx.x >= 2048) {
        int w = ((blockIdx.x - 2048) * 256 + tid) >> 5;
        int lane = tid & 31;
        if (w >= VOCAB) return;
        const float* row = emb + (size_t)w * K_DIM;
        double s = 0.0;
        #pragma unroll
        for (int h = 0; h < 2; ++h) {
            float4 e = *(const float4*)(row + lane * 4 + h * 128);
            int col = 2 * lane + h * 64;
            g_ebB[w * 128 + col]     = pack_bf16(e.x, e.y);
            g_ebB[w * 128 + col + 1] = pack_bf16(e.z, e.w);
            s += (double)e.x * e.x + (double)e.y * e.y + (double)e.z * e.z + (double)e.w * e.w;
        }
        #pragma unroll
        for (int off = 16; off; off >>= 1)
            s += __shfl_down_sync(0xffffffffu, s, off);
        if (lane == 0) g_se[w] = (float)s;
        return;
    }
    const int g = blockIdx.x;
    const float4* xb = (const float4*)(x + (size_t)g * AV);
    #pragma unroll
    for (int it = 0; it < 4; ++it)
        *(float4*)(sx + (tid + it * 256) * 4) = xb[tid + it * 256];
    __syncthreads();
    {
        int v = tid & 15, cg = tid >> 4;
        #pragma unroll
        for (int j = 0; j < 8; ++j) {
            int c = cg * 8 + j;
            float za = sx[(2 * c) * 16 + v];
            float zb = sx[(2 * c + 1) * 16 + v];
            g_xb[(size_t)(g * 16 + v) * 128 + c] = pack_bf16(za, zb);
        }
    }
    {
        int vv = tid & 15, seg = tid >> 4;
        float s = 0.0f, cc = 0.0f;
        #pragma unroll
        for (int k = 0; k < 16; ++k)
            sq_acc(sx[(seg * 16 + k) * 16 + vv], s, cc);
        scr[(vv * 16 + seg) * 2] = s;
        scr[(vv * 16 + seg) * 2 + 1] = cc;
    }
    __syncthreads();
    if (tid < 16) {
        double tot = 0.0;
        #pragma unroll
        for (int seg = 0; seg < 16; ++seg) {
            tot += (double)scr[(tid * 16 + seg) * 2];
            tot += (double)scr[(tid * 16 + seg) * 2 + 1];
        }
        g_sz[g * 16 + tid] = (float)tot;
    }
}

extern __shared__ unsigned char smem_raw[];

// ---------------- main: coarse bf16 HMMA + exact fp32 re-rank + writeback ----------------
__global__ void __launch_bounds__(BLK, 1)
vq_kernel(const float* __restrict__ x, const float* __restrict__ emb,
          float* __restrict__ out, int out_size) {
    float* se_s  = (float*)(smem_raw + SE_OFF);
    float* szf   = (float*)(smem_raw + SZF_OFF);
    float* cminw = (float*)(smem_raw + CMIN_OFF);
    float* thr_s = (float*)(smem_raw + THR_OFF);
    int*   cnt_s = (int*)(smem_raw + CNT_OFF);
    int*   cand_s = (int*)(smem_raw + CAND_OFF);
    int*   tok_s = (int*)(smem_raw + TOK_OFF);
    const uint32_t sb = smem_u32(smem_raw);

    const int tid = threadIdx.x;
    const int lane = tid & 31, wid = tid >> 5;
    const int mw = (wid & 7) * 16;        // warp m offset (0..112)
    const int nw = (wid >> 3) * 64;       // warp n half (0/64)
    const int gr = lane >> 2, gc = (lane & 3) * 2;
    const int m0 = blockIdx.x * M_TILE;

    // ldmatrix lane address components
    const uint32_t aAddr = sb + A_OFF
        + (uint32_t)(mw + (lane & 7) + ((lane >> 3) & 1) * 8) * PA_B
        + ((lane >> 4) & 1) * 16;
    const uint32_t bAddr = sb + B_OFF
        + (uint32_t)(nw + (lane & 7) + (lane >> 4) * 8) * PB_B
        + ((lane >> 3) & 1) * 16;

    // ---- stage 0 B prefetch into buf 0 (row = tid>>2, quarter = tid&3 -> 2x16B)
    {
        const int row = tid >> 2, q = tid & 3;
        const char* src = (const char*)g_ebB + (size_t)row * 512 + q * 32;
        const uint32_t dst = sb + B_OFF + row * PB_B + q * 32;
        cpa16(dst, src); cpa16(dst + 16, src + 16);
        cp_commit();
    }
    // ---- A tile (bf16, full K) via cp.async: row = tid>>2, 8 chunks of 16B
    {
        const int row = tid >> 2;
        const char* src = (const char*)g_xb + (size_t)(m0 + row) * 512;
        const uint32_t dst = sb + A_OFF + row * PA_B;
        #pragma unroll
        for (int j = 0; j < 8; ++j) {
            int ch = (tid & 3) + 4 * j;
            cpa16(dst + ch * 16, src + ch * 16);
        }
        cp_commit();
    }
    // ---- stage se, sz
    for (int i = tid; i < VOCAB; i += BLK) se_s[i] = g_se[i];
    if (tid < M_TILE) szf[tid] = g_sz[m0 + tid];

    // ---- coarse fold state
    float d[8][4];
    #pragma unroll
    for (int f = 0; f < 8; ++f)
        #pragma unroll
        for (int j = 0; j < 4; ++j) d[f][j] = 0.0f;
    const float INFV = __int_as_float(0x7f800000);
    float T0[3] = {INFV, INFV, INFV}, T1[3] = {INFV, INFV, INFV};
    int   N0[3] = {0, 0, 0},          N1[3] = {0, 0, 0};

    // ---- main loop: 8 n-tiles x 4 k-chunks (64k each)
    #pragma unroll 1
    for (int s = 0; s < 32; ++s) {
        cp_wait0();
        __syncthreads();
        const int t = s >> 2, c = s & 3, buf = s & 1;
        // prefetch next chunk into buf^1
        if (s + 1 < 32) {
            const int t2 = (s + 1) >> 2, c2 = (s + 1) & 3;
            const int row = tid >> 2, q = tid & 3;
            const char* src = (const char*)g_ebB + (size_t)(t2 * 128 + row) * 512
                            + c2 * 128 + q * 32;
            const uint32_t dst = sb + B_OFF + (buf ^ 1) * B_TILE_B + row * PB_B + q * 32;
            cpa16(dst, src); cpa16(dst + 16, src + 16);
            cp_commit();
        }
        // compute: 4 k16 steps on buf
        #pragma unroll
        for (int kk = 0; kk < 4; ++kk) {
            uint32_t a0, a1, a2, a3;
            ldsm4(a0, a1, a2, a3, aAddr + c * 128 + kk * 32);
            #pragma unroll
            for (int fp = 0; fp < 4; ++fp) {
                uint32_t b0, b1, b2, b3;
                ldsm4(b0, b1, b2, b3, bAddr + buf * B_TILE_B + fp * (16 * PB_B) + kk * 32);
                mma_bf16(d[2 * fp],     a0, a1, a2, a3, b0, b1);
                mma_bf16(d[2 * fp + 1], a0, a1, a2, a3, b2, b3);
            }
        }
        // end of n-tile: coarse dist (se - 2*dot, no sz) + top-3 fold
        if (c == 3) {
            #pragma unroll
            for (int f = 0; f < 8; ++f) {
                const int nn = t * 128 + nw + f * 8 + gc;
                const float se0 = se_s[nn], se1 = se_s[nn + 1];
                top3(T0, N0, fmaf(-2.0f, d[f][0], se0), nn);
                top3(T0, N0, fmaf(-2.0f, d[f][1], se1), nn + 1);
                top3(T1, N1, fmaf(-2.0f, d[f][2], se0), nn);
                top3(T1, N1, fmaf(-2.0f, d[f][3], se1), nn + 1);
                d[f][0] = 0.0f; d[f][1] = 0.0f; d[f][2] = 0.0f; d[f][3] = 0.0f;
            }
        }
    }

    // ---- coarse min per m: quad-reduce best1, combine across n-halves
    {
        float v0 = T0[0], v1 = T1[0];
        #pragma unroll
        for (int off = 1; off <= 2; off <<= 1) {
            v0 = fminf(v0, __shfl_xor_sync(0xffffffffu, v0, off));
            v1 = fminf(v1, __shfl_xor_sync(0xffffffffu, v1, off));
        }
        if ((lane & 3) == 0) {
            cminw[(wid >> 3) * 128 + mw + gr]     = v0;
            cminw[(wid >> 3) * 128 + mw + gr + 8] = v1;
        }
    }
    __syncthreads();
    if (tid < M_TILE) {
        thr_s[tid] = fminf(cminw[tid], cminw[128 + tid]) + MARGIN;
        cnt_s[tid] = 0;
    }
    __syncthreads();
    // ---- append candidates within margin
    {
        const int mloc0 = mw + gr, mloc1 = mw + gr + 8;
        const float th0 = thr_s[mloc0], th1 = thr_s[mloc1];
        #pragma unroll
        for (int i = 0; i < 3; ++i) {
            if (T0[i] <= th0) {
                int pos = atomicAdd(&cnt_s[mloc0], 1);
                if (pos < 12) cand_s[mloc0 * 12 + pos] = N0[i];
            }
            if (T1[i] <= th1) {
                int pos = atomicAdd(&cnt_s[mloc1], 1);
                if (pos < 12) cand_s[mloc1 * 12 + pos] = N1[i];
            }
        }
    }
    __syncthreads();

    // ---- exact fp32 re-rank (thread per m row), ref rounding chain + index tie-break
    if (tid < M_TILE) {
        const int mg = m0 + tid;
        const float* xr = x + (size_t)(mg >> 4) * AV + (mg & 15);
        const float szm = szf[tid];
        int nc = cnt_s[tid]; if (nc > 12) nc = 12;
        float bestD = INFV; int bestN = 0x7fffffff;
        for (int i = 0; i < nc; ++i) {
            const int n = cand_s[tid * 12 + i];
            const float* er = emb + (size_t)n * K_DIM;
            float p0 = 0.f, p1 = 0.f, p2 = 0.f, p3 = 0.f;
            #pragma unroll 4
            for (int a = 0; a < K_DIM; a += 4) {
                p0 = fmaf(xr[(a + 0) * 16], er[a + 0], p0);
                p1 = fmaf(xr[(a + 1) * 16], er[a + 1], p1);
                p2 = fmaf(xr[(a + 2) * 16], er[a + 2], p2);
                p3 = fmaf(xr[(a + 3) * 16], er[a + 3], p3);
            }
            const float dot = __fadd_rn(__fadd_rn(p0, p1), __fadd_rn(p2, p3));
            const float tv = __fadd_rn(szm, se_s[n]);   // fl(sz + se)
            const float dist = fmaf(-2.0f, dot, tv);    // == fl(t - fl(2*dot))
            if (dist < bestD || (dist == bestD && n < bestN)) { bestD = dist; bestN = n; }
        }
        tok_s[tid] = bestN;
    }
    __syncthreads();

    // ---- outputs: z_q | decoder_input | tokens (as float), guarded by out_size
    float* out_zq  = out;
    float* out_dec = out + (size_t)N_Q * K_DIM;
    float* out_tok = out + (size_t)2 * N_Q * K_DIM;
    const long long need_dec = 2LL * N_Q * K_DIM;
    const bool wd = (long long)out_size >= need_dec;
    const bool wt = (long long)out_size >= need_dec + N_Q;

    if (wt && tid < M_TILE) out_tok[m0 + tid] = (float)tok_s[tid];

    const int bl0 = blockIdx.x * 8;
    #pragma unroll
    for (int g = 0; g < 8; ++g) {
        const float* xr = x + (size_t)(bl0 + g) * AV;
        float* zr = out_zq  + (size_t)(bl0 + g) * AV;
        float* dr = out_dec + (size_t)(bl0 + g) * AV;
        for (int idx = tid * 4; idx < AV; idx += BLK * 4) {
            int a = idx >> 4, v0 = idx & 15;
            float4 xv = *(const float4*)(xr + idx);
            float4 q;
            q.x = emb[(size_t)tok_s[g * 16 + v0 + 0] * K_DIM + a];
            q.y = emb[(size_t)tok_s[g * 16 + v0 + 1] * K_DIM + a];
            q.z = emb[(size_t)tok_s[g * 16 + v0 + 2] * K_DIM + a];
            q.w = emb[(size_t)tok_s[g * 16 + v0 + 3] * K_DIM + a];
            *(float4*)(zr + idx) = q;
            if (wd) {
                float4 dv;
                dv.x = xv.x + (q.x - xv.x);
                dv.y = xv.y + (q.y - xv.y);
                dv.z = xv.z + (q.z - xv.z);
                dv.w = xv.w + (q.w - xv.w);
                *(float4*)(dr + idx) = dv;
            }
        }
    }
}

extern "C" void kernel_launch(void* const* d_in, const int* in_sizes, int n_in,
                              void* d_out, int out_size) {
    const float* x   = (const float*)d_in[0];
    const float* emb = (const float*)d_in[1];
    float* out = (float*)d_out;
    (void)in_sizes; (void)n_in;

    cudaFuncSetAttribute(vq_kernel, cudaFuncAttributeMaxDynamicSharedMemorySize, SMEM_BYTES);

    prep_all<<<2176, 256>>>(x, emb);
    vq_kernel<<<N_Q / M_TILE, BLK, SMEM_BYTES>>>(x, emb, out, out_size);
}

// round 9
// speedup vs baseline: 3.3212x; 1.1913x over previous
#include <cuda_runtime.h>
#include <cuda_bf16.h>
#include <cstdint>

#define BLK     512
#define M_TILE  256
#define K_DIM   256
#define VOCAB   1024
#define N_Q     32768
#define AV      4096
#define PT_B    144          // tile row pitch bytes (128 data + 16 pad)
#define MARGIN  3.2e-4f

// ---- smem layout (bytes) ----
#define A_OFF     0
#define A_CHUNK_B (256 * PT_B)                // 36864 per k64 chunk
#define B_OFF     (4 * A_CHUNK_B)             // 147456 (A: all 4 chunks resident)
#define B_TILE_B  (128 * PT_B)                // 18432 per buffer
#define SE_OFF    (B_OFF + 2 * B_TILE_B)      // 184320
#define SZF_OFF   (SE_OFF + 4096)             // 188416 (256 floats)
#define CMIN_OFF  (SZF_OFF + 1024)            // 189440 (512 floats)
#define THR_OFF   (CMIN_OFF + 2048)           // 191488 (256 floats)
#define CNT_OFF   (THR_OFF + 1024)            // 192512 (256 ints)
#define CAND_OFF  (CNT_OFF + 1024)            // 193536 (256*12 ints)
#define TOK_OFF   (CAND_OFF + 12288)          // 205824
#define SMEM_BYTES (TOK_OFF + 1024)           // 206848

__device__ unsigned int g_xb[N_Q * 128];      // x as bf16 pairs: [m][kpair]
__device__ unsigned int g_ebB[VOCAB * 128];   // emb as bf16 pairs: [n][kpair]
__device__ float g_se[VOCAB];
__device__ float g_sz[N_Q];

// ---------------- helpers ----------------
__device__ __forceinline__ uint32_t smem_u32(const void* p) {
    uint32_t a;
    asm("{ .reg .u64 t; cvta.to.shared.u64 t, %1; cvt.u32.u64 %0, t; }" : "=r"(a) : "l"(p));
    return a;
}
__device__ __forceinline__ void cpa16(uint32_t dst, const void* src) {
    asm volatile("cp.async.cg.shared.global [%0], [%1], 16;" :: "r"(dst), "l"(src));
}
__device__ __forceinline__ void cp_commit() { asm volatile("cp.async.commit_group;"); }
__device__ __forceinline__ void cp_wait0()  { asm volatile("cp.async.wait_group 0;" ::: "memory"); }

__device__ __forceinline__ void ldsm4(uint32_t& r0, uint32_t& r1, uint32_t& r2, uint32_t& r3,
                                      uint32_t addr) {
    asm volatile("ldmatrix.sync.aligned.m8n8.x4.shared.b16 {%0,%1,%2,%3}, [%4];"
                 : "=r"(r0), "=r"(r1), "=r"(r2), "=r"(r3) : "r"(addr));
}
__device__ __forceinline__ void mma_bf16(float* d, uint32_t a0, uint32_t a1, uint32_t a2,
                                         uint32_t a3, uint32_t b0, uint32_t b1) {
    asm volatile("mma.sync.aligned.m16n8k16.row.col.f32.bf16.bf16.f32 "
                 "{%0,%1,%2,%3}, {%4,%5,%6,%7}, {%8,%9}, {%0,%1,%2,%3};"
                 : "+f"(d[0]), "+f"(d[1]), "+f"(d[2]), "+f"(d[3])
                 : "r"(a0), "r"(a1), "r"(a2), "r"(a3), "r"(b0), "r"(b1));
}

__device__ __forceinline__ unsigned pack_bf16(float x, float y) {
    return (unsigned)__bfloat16_as_ushort(__float2bfloat16(x))
         | ((unsigned)__bfloat16_as_ushort(__float2bfloat16(y)) << 16);
}

// exact-product compensated accumulate: (s,c) += z*z
__device__ __forceinline__ void sq_acc(float z, float& s, float& c) {
    float p = __fmul_rn(z, z);
    float e = fmaf(z, z, -p);
    float t = __fadd_rn(s, p);
    float bb = __fsub_rn(t, s);
    float err = __fadd_rn(__fsub_rn(s, __fsub_rn(t, bb)), __fsub_rn(p, bb));
    s = t;
    c = __fadd_rn(c, __fadd_rn(err, e));
}

__device__ __forceinline__ void top2(float* T, int* N, float v, int n) {
    if (v < T[1]) {
        if (v < T[0]) { T[1] = T[0]; N[1] = N[0]; T[0] = v; N[0] = n; }
        else          { T[1] = v;    N[1] = n; }
    }
}

// ---------------- merged prep (256 threads/block) ----------------
__global__ void prep_all(const float* __restrict__ x, const float* __restrict__ emb) {
    __shared__ float sx[4096];
    __shared__ float scr[512];
    const int tid = threadIdx.x;
    if (blockIdx.x >= 2048) {
        int w = ((blockIdx.x - 2048) * 256 + tid) >> 5;
        int lane = tid & 31;
        if (w >= VOCAB) return;
        const float* row = emb + (size_t)w * K_DIM;
        double s = 0.0;
        #pragma unroll
        for (int h = 0; h < 2; ++h) {
            float4 e = *(const float4*)(row + lane * 4 + h * 128);
            int col = 2 * lane + h * 64;
            g_ebB[w * 128 + col]     = pack_bf16(e.x, e.y);
            g_ebB[w * 128 + col + 1] = pack_bf16(e.z, e.w);
            s += (double)e.x * e.x + (double)e.y * e.y + (double)e.z * e.z + (double)e.w * e.w;
        }
        #pragma unroll
        for (int off = 16; off; off >>= 1)
            s += __shfl_down_sync(0xffffffffu, s, off);
        if (lane == 0) g_se[w] = (float)s;
        return;
    }
    const int g = blockIdx.x;
    const float4* xb = (const float4*)(x + (size_t)g * AV);
    #pragma unroll
    for (int it = 0; it < 4; ++it)
        *(float4*)(sx + (tid + it * 256) * 4) = xb[tid + it * 256];
    __syncthreads();
    {
        int v = tid & 15, cg = tid >> 4;
        #pragma unroll
        for (int j = 0; j < 8; ++j) {
            int c = cg * 8 + j;
            float za = sx[(2 * c) * 16 + v];
            float zb = sx[(2 * c + 1) * 16 + v];
            g_xb[(size_t)(g * 16 + v) * 128 + c] = pack_bf16(za, zb);
        }
    }
    {
        int vv = tid & 15, seg = tid >> 4;
        float s = 0.0f, cc = 0.0f;
        #pragma unroll
        for (int k = 0; k < 16; ++k)
            sq_acc(sx[(seg * 16 + k) * 16 + vv], s, cc);
        scr[(vv * 16 + seg) * 2] = s;
        scr[(vv * 16 + seg) * 2 + 1] = cc;
    }
    __syncthreads();
    if (tid < 16) {
        double tot = 0.0;
        #pragma unroll
        for (int seg = 0; seg < 16; ++seg) {
            tot += (double)scr[(tid * 16 + seg) * 2];
            tot += (double)scr[(tid * 16 + seg) * 2 + 1];
        }
        g_sz[g * 16 + tid] = (float)tot;
    }
}

extern __shared__ unsigned char smem_raw[];

// ---------------- main: coarse bf16 HMMA + exact fp32 re-rank + writeback ----------------
__global__ void __launch_bounds__(BLK, 1)
vq_kernel(const float* __restrict__ x, const float* __restrict__ emb,
          float* __restrict__ out, int out_size) {
    float* se_s  = (float*)(smem_raw + SE_OFF);
    float* szf   = (float*)(smem_raw + SZF_OFF);
    float* cminw = (float*)(smem_raw + CMIN_OFF);
    float* thr_s = (float*)(smem_raw + THR_OFF);
    int*   cnt_s = (int*)(smem_raw + CNT_OFF);
    int*   cand_s = (int*)(smem_raw + CAND_OFF);
    int*   tok_s = (int*)(smem_raw + TOK_OFF);
    const uint32_t sb = smem_u32(smem_raw);

    const int tid = threadIdx.x;
    const int lane = tid & 31, wid = tid >> 5;
    const int mw = (wid & 7) * 32;        // warp m offset (0..224)
    const int half = wid >> 3;            // n half (0/1)
    const int nw = half * 64;
    const int gr = lane >> 2, gc = (lane & 3) * 2;
    const int m0 = blockIdx.x * M_TILE;

    // ldmatrix lane address bases (pitch PT_B both tiles)
    const uint32_t aLane = sb + A_OFF
        + (uint32_t)(mw + (lane & 7) + ((lane >> 3) & 1) * 8) * PT_B
        + ((lane >> 4) & 1) * 16;
    const uint32_t bLane = sb + B_OFF
        + (uint32_t)(nw + (lane & 7) + (lane >> 4) * 8) * PT_B
        + ((lane >> 3) & 1) * 16;

    // ---- stage 0 prefetch: A chunk 0 + B(t0,c0) into buf 0
    {
        const int arow = tid >> 1, ah = (tid & 1) * 64;
        const char* asrc = (const char*)g_xb + (size_t)(m0 + arow) * 512 + ah;
        const uint32_t adst = sb + A_OFF + arow * PT_B + ah;
        #pragma unroll
        for (int j = 0; j < 4; ++j) cpa16(adst + j * 16, asrc + j * 16);
        const int brow = tid >> 2, q = tid & 3;
        const char* bsrc = (const char*)g_ebB + (size_t)brow * 512 + q * 32;
        const uint32_t bdst = sb + B_OFF + brow * PT_B + q * 32;
        cpa16(bdst, bsrc); cpa16(bdst + 16, bsrc + 16);
        cp_commit();
    }
    // ---- stage se, sz
    for (int i = tid; i < VOCAB; i += BLK) se_s[i] = g_se[i];
    if (tid < M_TILE) szf[tid] = g_sz[m0 + tid];

    // ---- coarse fold state: d[mf][f][4], top2 per m-position
    float d[2][8][4];
    #pragma unroll
    for (int mf = 0; mf < 2; ++mf)
        #pragma unroll
        for (int f = 0; f < 8; ++f)
            #pragma unroll
            for (int j = 0; j < 4; ++j) d[mf][f][j] = 0.0f;
    const float INFV = __int_as_float(0x7f800000);
    float T[4][2]; int N[4][2];
    #pragma unroll
    for (int mp = 0; mp < 4; ++mp) { T[mp][0] = INFV; T[mp][1] = INFV; N[mp][0] = 0; N[mp][1] = 0; }

    // ---- main loop: 8 n-tiles x 4 k-chunks
    #pragma unroll 1
    for (int s = 0; s < 32; ++s) {
        cp_wait0();
        __syncthreads();
        const int t = s >> 2, c = s & 3, buf = s & 1;
        // prefetch next stage
        if (s + 1 < 32) {
            const int t2 = (s + 1) >> 2, c2 = (s + 1) & 3;
            if (s + 1 < 4) {   // A chunks: load once, chunk index == stage
                const int arow = tid >> 1, ah = (tid & 1) * 64;
                const char* asrc = (const char*)g_xb + (size_t)(m0 + arow) * 512
                                 + (s + 1) * 128 + ah;
                const uint32_t adst = sb + A_OFF + (s + 1) * A_CHUNK_B + arow * PT_B + ah;
                #pragma unroll
                for (int j = 0; j < 4; ++j) cpa16(adst + j * 16, asrc + j * 16);
            }
            const int brow = tid >> 2, q = tid & 3;
            const char* bsrc = (const char*)g_ebB + (size_t)(t2 * 128 + brow) * 512
                             + c2 * 128 + q * 32;
            const uint32_t bdst = sb + B_OFF + (buf ^ 1) * B_TILE_B + brow * PT_B + q * 32;
            cpa16(bdst, bsrc); cpa16(bdst + 16, bsrc + 16);
            cp_commit();
        }
        // compute: 4 k16 steps; A from resident chunk c, B from buf
        const uint32_t aC = aLane + c * A_CHUNK_B;
        const uint32_t bC = bLane + buf * B_TILE_B;
        #pragma unroll
        for (int kk = 0; kk < 4; ++kk) {
            uint32_t a0[4], a1[4];
            ldsm4(a0[0], a0[1], a0[2], a0[3], aC + kk * 32);
            ldsm4(a1[0], a1[1], a1[2], a1[3], aC + 16 * PT_B + kk * 32);
            #pragma unroll
            for (int fp = 0; fp < 4; ++fp) {
                uint32_t b0, b1, b2, b3;
                ldsm4(b0, b1, b2, b3, bC + fp * (16 * PT_B) + kk * 32);
                mma_bf16(d[0][2 * fp],     a0[0], a0[1], a0[2], a0[3], b0, b1);
                mma_bf16(d[0][2 * fp + 1], a0[0], a0[1], a0[2], a0[3], b2, b3);
                mma_bf16(d[1][2 * fp],     a1[0], a1[1], a1[2], a1[3], b0, b1);
                mma_bf16(d[1][2 * fp + 1], a1[0], a1[1], a1[2], a1[3], b2, b3);
            }
        }
        // end of n-tile: coarse dist (se - 2*dot) + top2 fold
        if (c == 3) {
            #pragma unroll
            for (int mf = 0; mf < 2; ++mf) {
                #pragma unroll
                for (int f = 0; f < 8; ++f) {
                    const int nn = t * 128 + nw + f * 8 + gc;
                    const float se0 = se_s[nn], se1 = se_s[nn + 1];
                    top2(T[mf * 2],     N[mf * 2],     fmaf(-2.0f, d[mf][f][0], se0), nn);
                    top2(T[mf * 2],     N[mf * 2],     fmaf(-2.0f, d[mf][f][1], se1), nn + 1);
                    top2(T[mf * 2 + 1], N[mf * 2 + 1], fmaf(-2.0f, d[mf][f][2], se0), nn);
                    top2(T[mf * 2 + 1], N[mf * 2 + 1], fmaf(-2.0f, d[mf][f][3], se1), nn + 1);
                    d[mf][f][0] = 0.0f; d[mf][f][1] = 0.0f;
                    d[mf][f][2] = 0.0f; d[mf][f][3] = 0.0f;
                }
            }
        }
    }

    // ---- coarse min per m-position: quad-reduce over gc lanes, write per half
    #pragma unroll
    for (int mp = 0; mp < 4; ++mp) {
        float v = T[mp][0];
        #pragma unroll
        for (int off = 1; off <= 2; off <<= 1)
            v = fminf(v, __shfl_xor_sync(0xffffffffu, v, off));
        if ((lane & 3) == 0)
            cminw[half * 256 + mw + (mp >> 1) * 16 + gr + (mp & 1) * 8] = v;
    }
    __syncthreads();
    if (tid < M_TILE) {
        thr_s[tid] = fminf(cminw[tid], cminw[256 + tid]) + MARGIN;
        cnt_s[tid] = 0;
    }
    __syncthreads();
    // ---- append candidates within margin
    #pragma unroll
    for (int mp = 0; mp < 4; ++mp) {
        const int mloc = mw + (mp >> 1) * 16 + gr + (mp & 1) * 8;
        const float th = thr_s[mloc];
        #pragma unroll
        for (int i = 0; i < 2; ++i) {
            if (T[mp][i] <= th) {
                int pos = atomicAdd(&cnt_s[mloc], 1);
                if (pos < 12) cand_s[mloc * 12 + pos] = N[mp][i];
            }
        }
    }
    __syncthreads();

    // ---- exact fp32 re-rank (thread per m row), ref rounding chain + index tie-break
    if (tid < M_TILE) {
        const int mg = m0 + tid;
        const float* xr = x + (size_t)(mg >> 4) * AV + (mg & 15);
        const float szm = szf[tid];
        int nc = cnt_s[tid]; if (nc > 12) nc = 12;
        float bestD = INFV; int bestN = 0x7fffffff;
        for (int i = 0; i < nc; ++i) {
            const int n = cand_s[tid * 12 + i];
            const float* er = emb + (size_t)n * K_DIM;
            float p0 = 0.f, p1 = 0.f, p2 = 0.f, p3 = 0.f;
            #pragma unroll 4
            for (int a = 0; a < K_DIM; a += 4) {
                p0 = fmaf(xr[(a + 0) * 16], er[a + 0], p0);
                p1 = fmaf(xr[(a + 1) * 16], er[a + 1], p1);
                p2 = fmaf(xr[(a + 2) * 16], er[a + 2], p2);
                p3 = fmaf(xr[(a + 3) * 16], er[a + 3], p3);
            }
            const float dot = __fadd_rn(__fadd_rn(p0, p1), __fadd_rn(p2, p3));
            const float tv = __fadd_rn(szm, se_s[n]);   // fl(sz + se)
            const float dist = fmaf(-2.0f, dot, tv);    // == fl(t - fl(2*dot))
            if (dist < bestD || (dist == bestD && n < bestN)) { bestD = dist; bestN = n; }
        }
        tok_s[tid] = bestN;
    }
    __syncthreads();

    // ---- outputs: z_q | decoder_input | tokens (as float), guarded by out_size
    float* out_zq  = out;
    float* out_dec = out + (size_t)N_Q * K_DIM;
    float* out_tok = out + (size_t)2 * N_Q * K_DIM;
    const long long need_dec = 2LL * N_Q * K_DIM;
    const bool wd = (long long)out_size >= need_dec;
    const bool wt = (long long)out_size >= need_dec + N_Q;

    if (wt && tid < M_TILE) out_tok[m0 + tid] = (float)tok_s[tid];

    const int bl0 = blockIdx.x * 16;
    #pragma unroll 1
    for (int g = 0; g < 16; ++g) {
        const float* xr = x + (size_t)(bl0 + g) * AV;
        float* zr = out_zq  + (size_t)(bl0 + g) * AV;
        float* dr = out_dec + (size_t)(bl0 + g) * AV;
        #pragma unroll
        for (int idx = tid * 4; idx < AV; idx += BLK * 4) {
            int a = idx >> 4, v0 = idx & 15;
            float4 xv = *(const float4*)(xr + idx);
            float4 q;
            q.x = emb[(size_t)tok_s[g * 16 + v0 + 0] * K_DIM + a];
            q.y = emb[(size_t)tok_s[g * 16 + v0 + 1] * K_DIM + a];
            q.z = emb[(size_t)tok_s[g * 16 + v0 + 2] * K_DIM + a];
            q.w = emb[(size_t)tok_s[g * 16 + v0 + 3] * K_DIM + a];
            *(float4*)(zr + idx) = q;
            if (wd) {
                float4 dv;
                dv.x = xv.x + (q.x - xv.x);
                dv.y = xv.y + (q.y - xv.y);
                dv.z = xv.z + (q.z - xv.z);
                dv.w = xv.w + (q.w - xv.w);
                *(float4*)(dr + idx) = dv;
            }
        }
    }
}

extern "C" void kernel_launch(void* const* d_in, const int* in_sizes, int n_in,
                              void* d_out, int out_size) {
    const float* x   = (const float*)d_in[0];
    const float* emb = (const float*)d_in[1];
    float* out = (float*)d_out;
    (void)in_sizes; (void)n_in;

    cudaFuncSetAttribute(vq_kernel, cudaFuncAttributeMaxDynamicSharedMemorySize, SMEM_BYTES);

    prep_all<<<2176, 256>>>(x, emb);
    vq_kernel<<<N_Q / M_TILE, BLK, SMEM_BYTES>>>(x, emb, out, out_size);
}